// round 15
// baseline (speedup 1.0000x reference)
#include <cuda_runtime.h>
#include <cuda_bf16.h>
#include <stdint.h>

#define NT 1024

// latent state stored pre-split as bf16 hi/lo
__device__ __nv_bfloat16 g_nhh[50000 * 128];
__device__ __nv_bfloat16 g_nhl[50000 * 128];
__device__ __nv_bfloat16 g_ehh[500000 * 128];
__device__ __nv_bfloat16 g_ehl[500000 * 128];
__device__ float g_rc[2 * 50000 * 128];
__device__ __nv_bfloat16 g_rch[50000 * 128];
__device__ __nv_bfloat16 g_rcl[50000 * 128];
__device__ float g_ps[50000 * 128];
__device__ float g_pr[50000 * 128];
__device__ __nv_bfloat16 g_whi[294912];
__device__ __nv_bfloat16 g_wlo[294912];
__device__ float g_b0p[4 * 128];

static __device__ __forceinline__ float gelu_f(float x) {
    float t = tanhf(0.7978845608028654f * (x + 0.044715f * x * x * x));
    return 0.5f * x * (1.0f + t);
}
static __device__ __forceinline__ float wred(float v) {
#pragma unroll
    for (int o = 16; o; o >>= 1) v += __shfl_xor_sync(0xffffffffu, v, o);
    return v;
}
static __device__ __forceinline__ uint32_t packh(float x, float y) {
    __nv_bfloat162 h; h.x = __float2bfloat16(x); h.y = __float2bfloat16(y);
    return *(uint32_t*)&h;
}
static __device__ __forceinline__ uint32_t packl(float x, float y, uint32_t hw) {
    __nv_bfloat162 hh = *(__nv_bfloat162*)&hw;
    __nv_bfloat162 l;
    l.x = __float2bfloat16(x - __bfloat162float(hh.x));
    l.y = __float2bfloat16(y - __bfloat162float(hh.y));
    return *(uint32_t*)&l;
}
static __device__ __forceinline__ void mmabf(float* d, const uint32_t* a, const uint32_t* b) {
    asm volatile(
        "mma.sync.aligned.m16n8k16.row.col.f32.bf16.bf16.f32 "
        "{%0,%1,%2,%3}, {%4,%5,%6,%7}, {%8,%9}, {%0,%1,%2,%3};"
        : "+f"(d[0]), "+f"(d[1]), "+f"(d[2]), "+f"(d[3])
        : "r"(a[0]), "r"(a[1]), "r"(a[2]), "r"(a[3]), "r"(b[0]), "r"(b[1]));
}
static __device__ __forceinline__ uint32_t s2u(const void* p) {
    return (uint32_t)__cvta_generic_to_shared(p);
}
static __device__ __forceinline__ void ldm4(uint32_t* r, uint32_t a) {
    asm volatile("ldmatrix.sync.aligned.m8n8.x4.shared.b16 {%0,%1,%2,%3}, [%4];"
        : "=r"(r[0]), "=r"(r[1]), "=r"(r[2]), "=r"(r[3]) : "r"(a));
}
static __device__ __forceinline__ void red4(float* dst, float4 v) {
    asm volatile("red.global.add.v4.f32 [%0], {%1,%2,%3,%4};"
        :: "l"(dst), "f"(v.x), "f"(v.y), "f"(v.z), "f"(v.w) : "memory");
}
static __device__ __forceinline__ float rec2(uint32_t h, uint32_t l, int hi) {
    __nv_bfloat162 hh = *(__nv_bfloat162*)&h;
    __nv_bfloat162 ll = *(__nv_bfloat162*)&l;
    return hi ? (__bfloat162float(hh.y) + __bfloat162float(ll.y))
              : (__bfloat162float(hh.x) + __bfloat162float(ll.x));
}
static __device__ __forceinline__ void cpa16(uint32_t d, const void* s, uint32_t sz) {
    asm volatile("cp.async.cg.shared.global [%0], [%1], 16, %2;"
        :: "r"(d), "l"(s), "r"(sz) : "memory");
}
#define CPCOMMIT() asm volatile("cp.async.commit_group;" ::: "memory")
#define CPWAIT1()  asm volatile("cp.async.wait_group 1;" ::: "memory")
#define CPWAIT0()  asm volatile("cp.async.wait_group 0;" ::: "memory")

// weight prep: 17 jobs — transpose W[K,128] -> [n][Kpad] bf16 hi/lo.
__global__ void prep_all(
    const float* q0, const float* q1, const float* q2, const float* q3,
    const float* q4, const float* q5, const float* q6, const float* q7,
    const float* q8)
{
    static const int SRC[17] = {0,1,2,3, 4,4,4,5, 4,4,4,5, 6,7,6,7, 8};
    static const int SOF[17] = {0,0,0,0, 0,16384,32768,0, 49408,65792,82176,16384, 0,0,33024,16384, 0};
    static const int KT[17]  = {7,128,3,128, 128,128,128,128, 128,128,128,128, 256,128,256,128, 128};
    static const int KPT[17] = {32,128,32,128, 128,128,128,128, 128,128,128,128, 256,128,256,128, 128};
    static const int OFT[17] = {0,4096,20480,24576, 40960,57344,73728,90112,
                                106496,122880,139264,155648, 172032,204800,221184,253952, 270336};
    const float* ws[9] = {q0,q1,q2,q3,q4,q5,q6,q7,q8};
    int j = blockIdx.y;
    int K = KT[j], Kpad = KPT[j], off = OFT[j];
    const float* W = ws[SRC[j]] + SOF[j];
    int idx = blockIdx.x * 256 + threadIdx.x;
    if (idx >= Kpad * 128) return;
    int k = idx >> 7, n = idx & 127;
    float x = (k < K) ? W[k * 128 + n] : 0.f;
    __nv_bfloat16 h = __float2bfloat16(x);
    __nv_bfloat16 l = __float2bfloat16(x - __bfloat162float(h));
    g_whi[off + n * Kpad + k] = h;
    g_wlo[off + n * Kpad + k] = l;
}

__global__ void bprep(const float* eu_W0, const float* eu_b0,
                      const float* nu_W0, const float* nu_b0, const float* glob) {
    int n = threadIdx.x;
    int l = blockIdx.x;
    float g0 = glob[0], g1 = glob[1];
    const float* W; const float* b; int K;
    if (l < 2) { W = eu_W0 + (size_t)l * 386 * 128; b = eu_b0 + l * 128; K = 386; }
    else       { W = nu_W0 + (size_t)(l - 2) * 258 * 128; b = nu_b0 + (l - 2) * 128; K = 258; }
    g_b0p[l * 128 + n] = b[n] + g0 * W[(size_t)(K - 2) * 128 + n] + g1 * W[(size_t)(K - 1) * 128 + n];
}

__global__ void zerok(float4* p, int n4) {
    int i = blockIdx.x * blockDim.x + threadIdx.x;
    if (i < n4) p[i] = make_float4(0.f, 0.f, 0.f, 0.f);
}

__global__ void rcsplit(const float* rc, __nv_bfloat16* rh, __nv_bfloat16* rl, int n2) {
    int i = blockIdx.x * 256 + threadIdx.x;
    if (i < n2) {
        float2 v = ((const float2*)rc)[i];
        uint32_t h = packh(v.x, v.y), l = packl(v.x, v.y, h);
        ((uint32_t*)rh)[i] = h;
        ((uint32_t*)rl)[i] = l;
    }
}

// smem (bytes, base dsm), M=256 tiles:
//   GEMM1 A bufs: 2 x 40960 at 0      (per buf: hi +0, lo +20480; row stride 80, 256 rows)
//   GEMM1 B bufs: 2 x 20480 at 81920  (per buf: hi +0, lo +10240; 128 rows x 80B)
//   A2:  hi 0..69632, lo 69632..139264 (256 rows, stride 272)
//   B2 bufs: 2 x 20480 at 139264
//   sD:  float[256][132] at 0 (135168)
#define SMEMSZ 180224

// MODE 0: embed  1: edge step  2: node step  3: decode (in0 = dec_W1)  4: PS/PR precompute
template <int MODE, int NC1, int KIN>
__global__ void __launch_bounds__(NT, 1) gk(
    int nrows, const float* __restrict__ in0, int w0off, int w1off,
    const float* __restrict__ b0, const float* __restrict__ b1,
    float* __restrict__ outp,
    __nv_bfloat16* __restrict__ outh, __nv_bfloat16* __restrict__ outl,
    const int* __restrict__ snd, const int* __restrict__ rcv,
    const __nv_bfloat16* __restrict__ nhh, const __nv_bfloat16* __restrict__ nhl,
    const __nv_bfloat16* __restrict__ ehh, const __nv_bfloat16* __restrict__ ehl,
    const __nv_bfloat16* __restrict__ rch, const __nv_bfloat16* __restrict__ rcl,
    const float* __restrict__ psp, const float* __restrict__ prp,
    float* __restrict__ rca,
    const float* __restrict__ lnsc, const float* __restrict__ lnbs, int write_ln)
{
    extern __shared__ char dsm[];
    float* sD = (float*)dsm;
    __shared__ int snd_sh[256], rcv_sh[256];
    __shared__ float sb0[128], sb1[128];

    const int tid = threadIdx.x, lane = tid & 31, warp = tid >> 5;
    const int row0 = blockIdx.x * 256;
    const int mr = (warp & 7) * 32, nc = (warp >> 3) * 32;   // 8x4 warp grid, 32x32 tiles
    const int g4 = lane >> 2, t4 = lane & 3;

    const uint32_t uA  = s2u(dsm);
    const uint32_t uB1 = uA + 81920;
    const uint32_t uB2 = uA + 139264;

    if (tid < 128) {
        sb0[tid] = b0[tid];
    } else if (tid < 256) {
        int j = tid - 128;
        if (MODE == 3) { if (j < 3) sb1[j] = b1[j]; }
        else sb1[j] = b1[j];
    } else if (MODE == 1 && tid >= 512) {
        int j = tid - 512;
        if (j < 256) snd_sh[j] = (row0 + j < nrows) ? snd[row0 + j] : 0;
        else         rcv_sh[j - 256] = (row0 + j - 256 < nrows) ? rcv[row0 + j - 256] : 0;
    }
    __syncthreads();

    const uint32_t a_row = (uint32_t)(lane & 15);
    const uint32_t a_ko  = (uint32_t)(lane >> 4) * 16u;
    const uint32_t b_row = (uint32_t)((lane & 7) + ((lane >> 4) << 3));
    const uint32_t b_ko  = (uint32_t)((lane >> 3) & 1) * 16u;

    const int cr = tid >> 2, cq = tid & 3;          // A copy: 256 rows x 4 quads
    const int bh2 = tid >> 9, bt = tid & 511;       // B copy: hi/lo split
    const int br = bt >> 2, bq = bt & 3;

    auto issueA = [&](int c, int bb) {
        int row = row0 + cr;
        int ko = cq * 8;
        const __nv_bfloat16 *ph, *pl;
        if (MODE == 1) {
            size_t o = (size_t)row * 128 + c * 32 + ko; ph = ehh + o; pl = ehl + o;
        } else if (MODE == 2) {
            if (c < 4) { size_t o = (size_t)row * 128 + c * 32 + ko; ph = nhh + o; pl = nhl + o; }
            else       { size_t o = (size_t)row * 128 + (c - 4) * 32 + ko; ph = rch + o; pl = rcl + o; }
        } else {
            size_t o = (size_t)row * 128 + c * 32 + ko; ph = nhh + o; pl = nhl + o;
        }
        uint32_t sz = (row < nrows) ? 16u : 0u;
        uint32_t d = uA + bb * 40960 + cr * 80 + cq * 16;
        cpa16(d, ph, sz);
        cpa16(d + 20480, pl, sz);
    };
    auto issueB1 = [&](int c, int bb) {
        const __nv_bfloat16* src = (bh2 ? g_wlo : g_whi) + (size_t)w0off + (size_t)br * (NC1 * 32) + c * 32 + bq * 8;
        uint32_t d = uB1 + bb * 20480 + br * 80 + bq * 16 + bh2 * 10240;
        cpa16(d, src, 16);
    };
    auto issueB2 = [&](int c, int bb) {
        const __nv_bfloat16* src = (bh2 ? g_wlo : g_whi) + (size_t)w1off + (size_t)br * 128 + c * 32 + bq * 8;
        uint32_t d = uB2 + bb * 20480 + br * 80 + bq * 16 + bh2 * 10240;
        cpa16(d, src, 16);
    };

    float acc[2][4][4];
#pragma unroll
    for (int mf = 0; mf < 2; mf++)
#pragma unroll
        for (int nf = 0; nf < 4; nf++)
#pragma unroll
            for (int q = 0; q < 4; q++) acc[mf][nf][q] = 0.f;

    auto mma1 = [&](int bb, int nks) {
#pragma unroll
        for (int ks = 0; ks < 2; ks++) {
            if (ks >= nks) break;
            uint32_t ah[2][4], al[2][4];
#pragma unroll
            for (int mf = 0; mf < 2; mf++) {
                uint32_t ra = uA + bb * 40960 + (uint32_t)(mr + mf * 16 + a_row) * 80u + (uint32_t)ks * 32u + a_ko;
                ldm4(ah[mf], ra);
                ldm4(al[mf], ra + 20480);
            }
#pragma unroll
            for (int np = 0; np < 2; np++) {
                uint32_t bh[4], bl[4];
                uint32_t rb = uB1 + bb * 20480 + (uint32_t)(nc + np * 16 + b_row) * 80u + (uint32_t)ks * 32u + b_ko;
                ldm4(bh, rb);
                ldm4(bl, rb + 10240);
#pragma unroll
                for (int mf = 0; mf < 2; mf++) {
                    mmabf(acc[mf][np * 2],     ah[mf], bh);
                    mmabf(acc[mf][np * 2],     ah[mf], bl);
                    mmabf(acc[mf][np * 2],     al[mf], bh);
                    mmabf(acc[mf][np * 2 + 1], ah[mf], bh + 2);
                    mmabf(acc[mf][np * 2 + 1], ah[mf], bl + 2);
                    mmabf(acc[mf][np * 2 + 1], al[mf], bh + 2);
                }
            }
        }
    };

    // ================= GEMM1 =================
    if (MODE != 0) {
        issueA(0, 0); issueB1(0, 0); CPCOMMIT();
#pragma unroll 1
        for (int c = 0; c < NC1; c++) {
            if (c + 1 < NC1) { issueA(c + 1, (c + 1) & 1); issueB1(c + 1, (c + 1) & 1); CPCOMMIT(); CPWAIT1(); }
            else CPWAIT0();
            __syncthreads();
            mma1(c & 1, 2);
            __syncthreads();
        }
    } else {
        {
            int row = row0 + cr;
            float v[8];
#pragma unroll
            for (int j = 0; j < 8; j++) {
                int k = cq * 8 + j;
                v[j] = (row < nrows && k < KIN) ? in0[(size_t)row * KIN + k] : 0.f;
            }
            uint4 hv, lv;
            hv.x = packh(v[0], v[1]); lv.x = packl(v[0], v[1], hv.x);
            hv.y = packh(v[2], v[3]); lv.y = packl(v[2], v[3], hv.y);
            hv.z = packh(v[4], v[5]); lv.z = packl(v[4], v[5], hv.z);
            hv.w = packh(v[6], v[7]); lv.w = packl(v[6], v[7], hv.w);
            *(uint4*)(dsm + cr * 80 + cq * 16) = hv;
            *(uint4*)(dsm + 20480 + cr * 80 + cq * 16) = lv;
            if (cr < 128) {
                *(uint4*)(dsm + 81920 + cr * 80 + cq * 16) = *(const uint4*)(g_whi + w0off + cr * 32 + cq * 8);
                *(uint4*)(dsm + 81920 + 10240 + cr * 80 + cq * 16) = *(const uint4*)(g_wlo + w0off + cr * 32 + cq * 8);
            }
        }
        __syncthreads();
        mma1(0, 1);
        __syncthreads();
    }

    // ================= MODE 4: store fp32 product, done =================
    if (MODE == 4) {
#pragma unroll
        for (int mf = 0; mf < 2; mf++)
#pragma unroll
            for (int nf = 0; nf < 4; nf++) {
                int r0 = mr + mf * 16 + g4, c0 = nc + nf * 8 + 2 * t4;
                int row1 = row0 + r0, row2 = row1 + 8;
                if (row1 < nrows)
                    *(float2*)(outp + (size_t)row1 * 128 + c0) = make_float2(acc[mf][nf][0], acc[mf][nf][1]);
                if (row2 < nrows)
                    *(float2*)(outp + (size_t)row2 * 128 + c0) = make_float2(acc[mf][nf][2], acc[mf][nf][3]);
            }
        return;
    }

    // prefetch first GEMM2 B chunk (overlaps epilogue 1)
    if (MODE != 3) { issueB2(0, 0); CPCOMMIT(); }

    // ================= epilogue 1: bias (+PS/PR for edges) + gelu =================
    if (MODE == 3) {
#pragma unroll
        for (int mf = 0; mf < 2; mf++)
#pragma unroll
            for (int nf = 0; nf < 4; nf++) {
                int r0 = mr + mf * 16 + g4, c0 = nc + nf * 8 + 2 * t4;
                sD[r0 * 132 + c0]           = gelu_f(acc[mf][nf][0] + sb0[c0]);
                sD[r0 * 132 + c0 + 1]       = gelu_f(acc[mf][nf][1] + sb0[c0 + 1]);
                sD[(r0 + 8) * 132 + c0]     = gelu_f(acc[mf][nf][2] + sb0[c0]);
                sD[(r0 + 8) * 132 + c0 + 1] = gelu_f(acc[mf][nf][3] + sb0[c0 + 1]);
            }
        __syncthreads();
        for (int i = tid; i < 256 * 3; i += NT) {
            int r = i / 3, cc = i - r * 3;
            int row = row0 + r;
            if (row < nrows) {
                float s = sb1[cc];
                const float* hr = sD + r * 132;
#pragma unroll 4
                for (int k = 0; k < 128; k++) s += hr[k] * __ldg(in0 + k * 3 + cc);
                outp[(size_t)row * 3 + cc] = s;
            }
        }
        return;
    }

    {
        uint32_t* A2hw = (uint32_t*)dsm;
        uint32_t* A2lw = (uint32_t*)(dsm + 69632);
#pragma unroll
        for (int mf = 0; mf < 2; mf++)
#pragma unroll
            for (int nf = 0; nf < 4; nf++) {
                int r0 = mr + mf * 16 + g4, c0 = nc + nf * 8 + 2 * t4;
                float a0 = acc[mf][nf][0] + sb0[c0];
                float a1 = acc[mf][nf][1] + sb0[c0 + 1];
                float a2 = acc[mf][nf][2] + sb0[c0];
                float a3 = acc[mf][nf][3] + sb0[c0 + 1];
                if (MODE == 1) {
                    float2 p0 = *(const float2*)(psp + (size_t)snd_sh[r0] * 128 + c0);
                    float2 q0 = *(const float2*)(prp + (size_t)rcv_sh[r0] * 128 + c0);
                    float2 p1 = *(const float2*)(psp + (size_t)snd_sh[r0 + 8] * 128 + c0);
                    float2 q1 = *(const float2*)(prp + (size_t)rcv_sh[r0 + 8] * 128 + c0);
                    a0 += p0.x + q0.x; a1 += p0.y + q0.y;
                    a2 += p1.x + q1.x; a3 += p1.y + q1.y;
                }
                float v0 = gelu_f(a0), v1 = gelu_f(a1), v2 = gelu_f(a2), v3 = gelu_f(a3);
                uint32_t h0 = packh(v0, v1), l0 = packl(v0, v1, h0);
                uint32_t h1 = packh(v2, v3), l1 = packl(v2, v3, h1);
                A2hw[r0 * 68 + (c0 >> 1)] = h0;       A2lw[r0 * 68 + (c0 >> 1)] = l0;
                A2hw[(r0 + 8) * 68 + (c0 >> 1)] = h1; A2lw[(r0 + 8) * 68 + (c0 >> 1)] = l1;
            }
    }
    __syncthreads();

    // ================= GEMM2: A2[256x128] @ W1 (B pipelined) =================
#pragma unroll
    for (int mf = 0; mf < 2; mf++)
#pragma unroll
        for (int nf = 0; nf < 4; nf++)
#pragma unroll
            for (int q = 0; q < 4; q++) acc[mf][nf][q] = 0.f;

#pragma unroll 1
    for (int c = 0; c < 4; c++) {
        if (c + 1 < 4) { issueB2(c + 1, (c + 1) & 1); CPCOMMIT(); CPWAIT1(); }
        else CPWAIT0();
        __syncthreads();
#pragma unroll
        for (int ks = 0; ks < 2; ks++) {
            uint32_t ah[2][4], al[2][4];
#pragma unroll
            for (int mf = 0; mf < 2; mf++) {
                uint32_t ra = uA + (uint32_t)(mr + mf * 16 + a_row) * 272u + (uint32_t)c * 64u + (uint32_t)ks * 32u + a_ko;
                ldm4(ah[mf], ra);
                ldm4(al[mf], ra + 69632);
            }
#pragma unroll
            for (int np = 0; np < 2; np++) {
                uint32_t bh[4], bl[4];
                uint32_t rb = uB2 + (uint32_t)((c & 1)) * 20480u + (uint32_t)(nc + np * 16 + b_row) * 80u + (uint32_t)ks * 32u + b_ko;
                ldm4(bh, rb);
                ldm4(bl, rb + 10240);
#pragma unroll
                for (int mf = 0; mf < 2; mf++) {
                    mmabf(acc[mf][np * 2],     ah[mf], bh);
                    mmabf(acc[mf][np * 2],     ah[mf], bl);
                    mmabf(acc[mf][np * 2],     al[mf], bh);
                    mmabf(acc[mf][np * 2 + 1], ah[mf], bh + 2);
                    mmabf(acc[mf][np * 2 + 1], ah[mf], bl + 2);
                    mmabf(acc[mf][np * 2 + 1], al[mf], bh + 2);
                }
            }
        }
        __syncthreads();
    }

    // ================= epilogue 2 =================
    if (MODE == 0) {
#pragma unroll
        for (int mf = 0; mf < 2; mf++)
#pragma unroll
            for (int nf = 0; nf < 4; nf++) {
                int r0 = mr + mf * 16 + g4, c0 = nc + nf * 8 + 2 * t4;
                int row1 = row0 + r0, row2 = row1 + 8;
                float v0 = acc[mf][nf][0] + sb1[c0], v1 = acc[mf][nf][1] + sb1[c0 + 1];
                float v2 = acc[mf][nf][2] + sb1[c0], v3 = acc[mf][nf][3] + sb1[c0 + 1];
                if (row1 < nrows) {
                    uint32_t h = packh(v0, v1);
                    *(uint32_t*)(outh + (size_t)row1 * 128 + c0) = h;
                    *(uint32_t*)(outl + (size_t)row1 * 128 + c0) = packl(v0, v1, h);
                }
                if (row2 < nrows) {
                    uint32_t h = packh(v2, v3);
                    *(uint32_t*)(outh + (size_t)row2 * 128 + c0) = h;
                    *(uint32_t*)(outl + (size_t)row2 * 128 + c0) = packl(v2, v3, h);
                }
            }
        return;
    }

#pragma unroll
    for (int mf = 0; mf < 2; mf++)
#pragma unroll
        for (int nf = 0; nf < 4; nf++) {
            int r0 = mr + mf * 16 + g4, c0 = nc + nf * 8 + 2 * t4;
            sD[r0 * 132 + c0]           = acc[mf][nf][0] + sb1[c0];
            sD[r0 * 132 + c0 + 1]       = acc[mf][nf][1] + sb1[c0 + 1];
            sD[(r0 + 8) * 132 + c0]     = acc[mf][nf][2] + sb1[c0];
            sD[(r0 + 8) * 132 + c0 + 1] = acc[mf][nf][3] + sb1[c0 + 1];
        }
    __syncthreads();

    if (MODE == 1) {
        for (int i = tid; i < 256 * 32; i += NT) {
            int r = i >> 5, q = i & 31;
            int row = row0 + r;
            if (row < nrows) {
                float4 v = *(float4*)(sD + r * 132 + q * 4);
                red4(rca + (size_t)rcv_sh[r] * 128 + q * 4, v);
            }
        }
    }
    if (write_ln) {
        float4 sc = *(const float4*)(lnsc + lane * 4);
        float4 bsv = *(const float4*)(lnbs + lane * 4);
        const __nv_bfloat16* skh = (MODE == 1) ? ehh : nhh;
        const __nv_bfloat16* skl = (MODE == 1) ? ehl : nhl;
        for (int r = warp; r < 256; r += 32) {
            int row = row0 + r;
            float4 x = *(float4*)(sD + r * 132 + lane * 4);
            if (row < nrows) {
                uint2 hh = *(const uint2*)(skh + (size_t)row * 128 + lane * 4);
                uint2 ll = *(const uint2*)(skl + (size_t)row * 128 + lane * 4);
                x.x += rec2(hh.x, ll.x, 0); x.y += rec2(hh.x, ll.x, 1);
                x.z += rec2(hh.y, ll.y, 0); x.w += rec2(hh.y, ll.y, 1);
            }
            float s = wred(x.x + x.y + x.z + x.w);
            float mean = s * (1.f / 128.f);
            float dx = x.x - mean, dy = x.y - mean, dz = x.z - mean, dw = x.w - mean;
            float vv = wred(dx * dx + dy * dy + dz * dz + dw * dw);
            float inv = rsqrtf(vv * (1.f / 128.f) + 1e-6f);
            if (row < nrows) {
                float o0 = dx * inv * sc.x + bsv.x, o1 = dy * inv * sc.y + bsv.y;
                float o2 = dz * inv * sc.z + bsv.z, o3 = dw * inv * sc.w + bsv.w;
                uint32_t p0 = packh(o0, o1), p1 = packh(o2, o3);
                *(uint2*)(outh + (size_t)row * 128 + lane * 4) = make_uint2(p0, p1);
                *(uint2*)(outl + (size_t)row * 128 + lane * 4) =
                    make_uint2(packl(o0, o1, p0), packl(o2, o3, p1));
            }
        }
    }
}

extern "C" void kernel_launch(void* const* d_in, const int* in_sizes, int n_in,
                              void* d_out, int out_size)
{
    const float* nodes  = (const float*)d_in[0];
    const float* edges  = (const float*)d_in[1];
    const float* glob   = (const float*)d_in[2];
    const int*   snd    = (const int*)d_in[3];
    const int*   rcv    = (const int*)d_in[4];
    const float* ne_W0  = (const float*)d_in[5];
    const float* ne_b0  = (const float*)d_in[6];
    const float* ne_W1  = (const float*)d_in[7];
    const float* ne_b1  = (const float*)d_in[8];
    const float* ee_W0  = (const float*)d_in[9];
    const float* ee_b0  = (const float*)d_in[10];
    const float* ee_W1  = (const float*)d_in[11];
    const float* ee_b1  = (const float*)d_in[12];
    const float* eu_W0  = (const float*)d_in[13];
    const float* eu_b0  = (const float*)d_in[14];
    const float* eu_W1  = (const float*)d_in[15];
    const float* eu_b1  = (const float*)d_in[16];
    const float* nu_W0  = (const float*)d_in[17];
    const float* nu_b0  = (const float*)d_in[18];
    const float* nu_W1  = (const float*)d_in[19];
    const float* nu_b1  = (const float*)d_in[20];
    const float* lnsc   = (const float*)d_in[21];
    const float* lnbs   = (const float*)d_in[22];
    const float* dec_W0 = (const float*)d_in[23];
    const float* dec_b0 = (const float*)d_in[24];
    const float* dec_W1 = (const float*)d_in[25];
    const float* dec_b1 = (const float*)d_in[26];
    float* out = (float*)d_out;

    const int N = in_sizes[0] / 7;
    const int E = in_sizes[1] / 3;

    __nv_bfloat16 *nhh, *nhl, *ehh, *ehl, *rch, *rcl;
    float *rc, *b0p, *ps, *pr;
    cudaGetSymbolAddress((void**)&nhh, g_nhh);
    cudaGetSymbolAddress((void**)&nhl, g_nhl);
    cudaGetSymbolAddress((void**)&ehh, g_ehh);
    cudaGetSymbolAddress((void**)&ehl, g_ehl);
    cudaGetSymbolAddress((void**)&rch, g_rch);
    cudaGetSymbolAddress((void**)&rcl, g_rcl);
    cudaGetSymbolAddress((void**)&rc,  g_rc);
    cudaGetSymbolAddress((void**)&b0p, g_b0p);
    cudaGetSymbolAddress((void**)&ps,  g_ps);
    cudaGetSymbolAddress((void**)&pr,  g_pr);

    const int O_NEW0 = 0, O_NEW1 = 4096, O_EEW0 = 20480, O_EEW1 = 24576;
    const int O_WE0 = 40960, O_WS0 = 57344, O_WR0 = 73728, O_EUW1_0 = 90112;
    const int O_WE1 = 106496, O_WS1 = 122880, O_WR1 = 139264, O_EUW1_1 = 155648;
    const int O_NUW0_0 = 172032, O_NUW1_0 = 204800, O_NUW0_1 = 221184, O_NUW1_1 = 253952;
    const int O_DEC0 = 270336;

    prep_all<<<dim3(128, 17), 256>>>(
        ne_W0, ne_W1, ee_W0, ee_W1, eu_W0, eu_W1, nu_W0, nu_W1, dec_W0);
    bprep<<<4, 128>>>(eu_W0, eu_b0, nu_W0, nu_b0, glob);

    cudaFuncSetAttribute(gk<0, 1, 7>,   cudaFuncAttributeMaxDynamicSharedMemorySize, SMEMSZ);
    cudaFuncSetAttribute(gk<0, 1, 3>,   cudaFuncAttributeMaxDynamicSharedMemorySize, SMEMSZ);
    cudaFuncSetAttribute(gk<1, 4, 386>, cudaFuncAttributeMaxDynamicSharedMemorySize, SMEMSZ);
    cudaFuncSetAttribute(gk<2, 8, 258>, cudaFuncAttributeMaxDynamicSharedMemorySize, SMEMSZ);
    cudaFuncSetAttribute(gk<3, 4, 128>, cudaFuncAttributeMaxDynamicSharedMemorySize, SMEMSZ);
    cudaFuncSetAttribute(gk<4, 4, 128>, cudaFuncAttributeMaxDynamicSharedMemorySize, SMEMSZ);

    const int nbN = (N + 255) / 256;
    const int nbE = (E + 255) / 256;

    zerok<<<(N * 32 + 255) / 256, 256>>>((float4*)rc, N * 32);
    zerok<<<(N * 32 + 255) / 256, 256>>>((float4*)(rc + (size_t)N * 128), N * 32);

    gk<0, 1, 7><<<nbN, NT, SMEMSZ>>>(N, nodes, O_NEW0, O_NEW1, ne_b0, ne_b1, nullptr,
        nhh, nhl, nullptr, nullptr, nhh, nhl, nullptr, nullptr, nullptr, nullptr,
        nullptr, nullptr, nullptr, nullptr, nullptr, 0);
    gk<0, 1, 3><<<nbE, NT, SMEMSZ>>>(E, edges, O_EEW0, O_EEW1, ee_b0, ee_b1, nullptr,
        ehh, ehl, nullptr, nullptr, nhh, nhl, nullptr, nullptr, nullptr, nullptr,
        nullptr, nullptr, nullptr, nullptr, nullptr, 0);

    for (int s = 0; s < 2; s++) {
        float* rcs = rc + (size_t)s * N * 128;
        gk<4, 4, 128><<<nbN, NT, SMEMSZ>>>(N, nullptr, s ? O_WS1 : O_WS0, 0, lnbs, lnbs, ps,
            nullptr, nullptr, nullptr, nullptr, nhh, nhl, nullptr, nullptr, nullptr, nullptr,
            nullptr, nullptr, nullptr, nullptr, nullptr, 0);
        gk<4, 4, 128><<<nbN, NT, SMEMSZ>>>(N, nullptr, s ? O_WR1 : O_WR0, 0, lnbs, lnbs, pr,
            nullptr, nullptr, nullptr, nullptr, nhh, nhl, nullptr, nullptr, nullptr, nullptr,
            nullptr, nullptr, nullptr, nullptr, nullptr, 0);
        gk<1, 4, 386><<<nbE, NT, SMEMSZ>>>(E, nullptr,
            s ? O_WE1 : O_WE0, s ? O_EUW1_1 : O_EUW1_0,
            b0p + s * 128, eu_b1 + s * 128, nullptr,
            ehh, ehl, snd, rcv, nhh, nhl, ehh, ehl, nullptr, nullptr,
            ps, pr, rcs, lnsc, lnbs, (s == 0) ? 1 : 0);
        rcsplit<<<(N * 64 + 255) / 256, 256>>>(rcs, rch, rcl, N * 64);
        gk<2, 8, 258><<<nbN, NT, SMEMSZ>>>(N, nullptr,
            s ? O_NUW0_1 : O_NUW0_0, s ? O_NUW1_1 : O_NUW1_0,
            b0p + (2 + s) * 128, nu_b1 + s * 128, nullptr,
            nhh, nhl, nullptr, nullptr, nhh, nhl, nullptr, nullptr, rch, rcl,
            nullptr, nullptr, nullptr, lnsc, lnbs, 1);
    }

    gk<3, 4, 128><<<nbN, NT, SMEMSZ>>>(N, dec_W1, O_DEC0, 0, dec_b0, dec_b1, out,
        nullptr, nullptr, nullptr, nullptr, nhh, nhl, nullptr, nullptr, nullptr, nullptr,
        nullptr, nullptr, nullptr, nullptr, nullptr, 0);
}

// round 16
// speedup vs baseline: 1.0572x; 1.0572x over previous
#include <cuda_runtime.h>
#include <cuda_bf16.h>
#include <stdint.h>

#define NT 512

// latent state stored pre-split as bf16 hi/lo
__device__ __nv_bfloat16 g_nhh[50000 * 128];
__device__ __nv_bfloat16 g_nhl[50000 * 128];
__device__ __nv_bfloat16 g_ehh[500000 * 128];
__device__ __nv_bfloat16 g_ehl[500000 * 128];
__device__ float g_rc[2 * 50000 * 128];
__device__ __nv_bfloat16 g_rch[50000 * 128];
__device__ __nv_bfloat16 g_rcl[50000 * 128];
__device__ float g_ps[50000 * 128];
__device__ float g_pr[50000 * 128];
__device__ __nv_bfloat16 g_whi[294912];
__device__ __nv_bfloat16 g_wlo[294912];
__device__ float g_b0p[4 * 128];

static __device__ __forceinline__ float gelu_f(float x) {
    float t = tanhf(0.7978845608028654f * (x + 0.044715f * x * x * x));
    return 0.5f * x * (1.0f + t);
}
static __device__ __forceinline__ float wred(float v) {
#pragma unroll
    for (int o = 16; o; o >>= 1) v += __shfl_xor_sync(0xffffffffu, v, o);
    return v;
}
static __device__ __forceinline__ uint32_t packh(float x, float y) {
    __nv_bfloat162 h; h.x = __float2bfloat16(x); h.y = __float2bfloat16(y);
    return *(uint32_t*)&h;
}
static __device__ __forceinline__ uint32_t packl(float x, float y, uint32_t hw) {
    __nv_bfloat162 hh = *(__nv_bfloat162*)&hw;
    __nv_bfloat162 l;
    l.x = __float2bfloat16(x - __bfloat162float(hh.x));
    l.y = __float2bfloat16(y - __bfloat162float(hh.y));
    return *(uint32_t*)&l;
}
static __device__ __forceinline__ void mmabf(float* d, const uint32_t* a, const uint32_t* b) {
    asm volatile(
        "mma.sync.aligned.m16n8k16.row.col.f32.bf16.bf16.f32 "
        "{%0,%1,%2,%3}, {%4,%5,%6,%7}, {%8,%9}, {%0,%1,%2,%3};"
        : "+f"(d[0]), "+f"(d[1]), "+f"(d[2]), "+f"(d[3])
        : "r"(a[0]), "r"(a[1]), "r"(a[2]), "r"(a[3]), "r"(b[0]), "r"(b[1]));
}
static __device__ __forceinline__ uint32_t s2u(const void* p) {
    return (uint32_t)__cvta_generic_to_shared(p);
}
static __device__ __forceinline__ void ldm4(uint32_t* r, uint32_t a) {
    asm volatile("ldmatrix.sync.aligned.m8n8.x4.shared.b16 {%0,%1,%2,%3}, [%4];"
        : "=r"(r[0]), "=r"(r[1]), "=r"(r[2]), "=r"(r[3]) : "r"(a));
}
static __device__ __forceinline__ void red4(float* dst, float4 v) {
    asm volatile("red.global.add.v4.f32 [%0], {%1,%2,%3,%4};"
        :: "l"(dst), "f"(v.x), "f"(v.y), "f"(v.z), "f"(v.w) : "memory");
}
static __device__ __forceinline__ float rec2(uint32_t h, uint32_t l, int hi) {
    __nv_bfloat162 hh = *(__nv_bfloat162*)&h;
    __nv_bfloat162 ll = *(__nv_bfloat162*)&l;
    return hi ? (__bfloat162float(hh.y) + __bfloat162float(ll.y))
              : (__bfloat162float(hh.x) + __bfloat162float(ll.x));
}
static __device__ __forceinline__ void cpa16(uint32_t d, const void* s, uint32_t sz) {
    asm volatile("cp.async.cg.shared.global [%0], [%1], 16, %2;"
        :: "r"(d), "l"(s), "r"(sz) : "memory");
}
#define CPCOMMIT() asm volatile("cp.async.commit_group;" ::: "memory")
#define CPWAIT1()  asm volatile("cp.async.wait_group 1;" ::: "memory")
#define CPWAIT0()  asm volatile("cp.async.wait_group 0;" ::: "memory")

// weight prep: 17 jobs — transpose W[K,128] -> [n][Kpad] bf16 hi/lo.
__global__ void prep_all(
    const float* q0, const float* q1, const float* q2, const float* q3,
    const float* q4, const float* q5, const float* q6, const float* q7,
    const float* q8)
{
    static const int SRC[17] = {0,1,2,3, 4,4,4,5, 4,4,4,5, 6,7,6,7, 8};
    static const int SOF[17] = {0,0,0,0, 0,16384,32768,0, 49408,65792,82176,16384, 0,0,33024,16384, 0};
    static const int KT[17]  = {7,128,3,128, 128,128,128,128, 128,128,128,128, 256,128,256,128, 128};
    static const int KPT[17] = {32,128,32,128, 128,128,128,128, 128,128,128,128, 256,128,256,128, 128};
    static const int OFT[17] = {0,4096,20480,24576, 40960,57344,73728,90112,
                                106496,122880,139264,155648, 172032,204800,221184,253952, 270336};
    const float* ws[9] = {q0,q1,q2,q3,q4,q5,q6,q7,q8};
    int j = blockIdx.y;
    int K = KT[j], Kpad = KPT[j], off = OFT[j];
    const float* W = ws[SRC[j]] + SOF[j];
    int idx = blockIdx.x * 256 + threadIdx.x;
    if (idx >= Kpad * 128) return;
    int k = idx >> 7, n = idx & 127;
    float x = (k < K) ? W[k * 128 + n] : 0.f;
    __nv_bfloat16 h = __float2bfloat16(x);
    __nv_bfloat16 l = __float2bfloat16(x - __bfloat162float(h));
    g_whi[off + n * Kpad + k] = h;
    g_wlo[off + n * Kpad + k] = l;
}

__global__ void bprep(const float* eu_W0, const float* eu_b0,
                      const float* nu_W0, const float* nu_b0, const float* glob) {
    int n = threadIdx.x;
    int l = blockIdx.x;
    float g0 = glob[0], g1 = glob[1];
    const float* W; const float* b; int K;
    if (l < 2) { W = eu_W0 + (size_t)l * 386 * 128; b = eu_b0 + l * 128; K = 386; }
    else       { W = nu_W0 + (size_t)(l - 2) * 258 * 128; b = nu_b0 + (l - 2) * 128; K = 258; }
    g_b0p[l * 128 + n] = b[n] + g0 * W[(size_t)(K - 2) * 128 + n] + g1 * W[(size_t)(K - 1) * 128 + n];
}

__global__ void rcsplit(const float* rc, __nv_bfloat16* rh, __nv_bfloat16* rl, int n2) {
    int i = blockIdx.x * 256 + threadIdx.x;
    if (i < n2) {
        float2 v = ((const float2*)rc)[i];
        uint32_t h = packh(v.x, v.y), l = packl(v.x, v.y, h);
        ((uint32_t*)rh)[i] = h;
        ((uint32_t*)rl)[i] = l;
    }
}

// smem (bytes, base dsm):
//   A bufs:  2 x 20480 at 0      (per buf: hi +0, lo +10240; row stride 80)
//   B bufs:  2 x 20480 at 69632
//   A2:      hi 0..34816, lo 34816..69632 (row stride 272)
//   sD:      float[128][132] at 0
#define SMEMSZ 110592

// MODE 0: embed  1: edge step  2: node step  3: decode (in0 = dec_W1)  4: PS/PR precompute (grid.y selects)
template <int MODE, int NC1, int KIN>
__global__ void __launch_bounds__(NT, 2) gk(
    int nrows, const float* __restrict__ in0, int w0off, int w1off,
    const float* __restrict__ b0, const float* __restrict__ b1,
    float* __restrict__ outp,
    __nv_bfloat16* __restrict__ outh, __nv_bfloat16* __restrict__ outl,
    const int* __restrict__ snd, const int* __restrict__ rcv,
    const __nv_bfloat16* __restrict__ nhh, const __nv_bfloat16* __restrict__ nhl,
    const __nv_bfloat16* __restrict__ ehh, const __nv_bfloat16* __restrict__ ehl,
    const __nv_bfloat16* __restrict__ rch, const __nv_bfloat16* __restrict__ rcl,
    const float* __restrict__ psp, const float* __restrict__ prp,
    float* __restrict__ rca,
    const float* __restrict__ lnsc, const float* __restrict__ lnbs, int write_ln)
{
    extern __shared__ char dsm[];
    float* sD = (float*)dsm;
    __shared__ int snd_sh[128], rcv_sh[128];
    __shared__ float sb0[128], sb1[128];

    const int tid = threadIdx.x, lane = tid & 31, warp = tid >> 5;
    const int row0 = blockIdx.x * 128;
    const int mr = (warp & 3) * 32, nc = (warp >> 2) * 32;
    const int g4 = lane >> 2, t4 = lane & 3;

    // MODE 4: blockIdx.y selects (W_s -> outp) vs (W_r -> rca-as-output)
    const int w0eff = (MODE == 4 && blockIdx.y) ? w1off : w0off;
    float* out4 = (MODE == 4 && blockIdx.y) ? rca : outp;

    const uint32_t uA = s2u(dsm);
    const uint32_t uB = uA + 69632;

    if (tid < 128) {
        sb0[tid] = b0[tid];
        if (MODE == 1) snd_sh[tid] = (row0 + tid < nrows) ? snd[row0 + tid] : 0;
    } else if (tid < 256) {
        int j = tid - 128;
        if (MODE == 3) { if (j < 3) sb1[j] = b1[j]; }
        else sb1[j] = b1[j];
        if (MODE == 1) rcv_sh[j] = (row0 + j < nrows) ? rcv[row0 + j] : 0;
    }
    __syncthreads();

    const uint32_t a_row = (uint32_t)(lane & 15);
    const uint32_t a_ko  = (uint32_t)(lane >> 4) * 16u;
    const uint32_t b_row = (uint32_t)((lane & 7) + ((lane >> 4) << 3));
    const uint32_t b_ko  = (uint32_t)((lane >> 3) & 1) * 16u;

    const int cr = tid >> 2, cq = tid & 3;

    auto issueA = [&](int c, int bb) {
        int row = row0 + cr;
        int ko = cq * 8;
        const __nv_bfloat16 *ph, *pl;
        if (MODE == 1) {
            size_t o = (size_t)row * 128 + c * 32 + ko; ph = ehh + o; pl = ehl + o;
        } else if (MODE == 2) {
            if (c < 4) { size_t o = (size_t)row * 128 + c * 32 + ko; ph = nhh + o; pl = nhl + o; }
            else       { size_t o = (size_t)row * 128 + (c - 4) * 32 + ko; ph = rch + o; pl = rcl + o; }
        } else {
            size_t o = (size_t)row * 128 + c * 32 + ko; ph = nhh + o; pl = nhl + o;
        }
        uint32_t sz = (row < nrows) ? 16u : 0u;
        uint32_t d = uA + bb * 20480 + cr * 80 + cq * 16;
        cpa16(d, ph, sz);
        cpa16(d + 10240, pl, sz);
    };
    auto issueB1 = [&](int c, int bb) {
        size_t o = (size_t)w0eff + (size_t)cr * (NC1 * 32) + c * 32 + cq * 8;
        uint32_t d = uB + bb * 20480 + cr * 80 + cq * 16;
        cpa16(d, g_whi + o, 16);
        cpa16(d + 10240, g_wlo + o, 16);
    };
    auto issueB2 = [&](int c, int bb) {
        size_t o = (size_t)w1off + (size_t)cr * 128 + c * 32 + cq * 8;
        uint32_t d = uB + bb * 20480 + cr * 80 + cq * 16;
        cpa16(d, g_whi + o, 16);
        cpa16(d + 10240, g_wlo + o, 16);
    };

    float acc[2][4][4];
#pragma unroll
    for (int mf = 0; mf < 2; mf++)
#pragma unroll
        for (int nf = 0; nf < 4; nf++)
#pragma unroll
            for (int q = 0; q < 4; q++) acc[mf][nf][q] = 0.f;

    auto mma1 = [&](int bb, int nks) {
#pragma unroll
        for (int ks = 0; ks < 2; ks++) {
            if (ks >= nks) break;
            uint32_t ah[2][4], al[2][4];
#pragma unroll
            for (int mf = 0; mf < 2; mf++) {
                uint32_t ra = uA + bb * 20480 + (uint32_t)(mr + mf * 16 + a_row) * 80u + (uint32_t)ks * 32u + a_ko;
                ldm4(ah[mf], ra);
                ldm4(al[mf], ra + 10240);
            }
#pragma unroll
            for (int np = 0; np < 2; np++) {
                uint32_t bh[4], bl[4];
                uint32_t rb = uB + bb * 20480 + (uint32_t)(nc + np * 16 + b_row) * 80u + (uint32_t)ks * 32u + b_ko;
                ldm4(bh, rb);
                ldm4(bl, rb + 10240);
#pragma unroll
                for (int mf = 0; mf < 2; mf++) {
                    mmabf(acc[mf][np * 2],     ah[mf], bh);
                    mmabf(acc[mf][np * 2],     ah[mf], bl);
                    mmabf(acc[mf][np * 2],     al[mf], bh);
                    mmabf(acc[mf][np * 2 + 1], ah[mf], bh + 2);
                    mmabf(acc[mf][np * 2 + 1], ah[mf], bl + 2);
                    mmabf(acc[mf][np * 2 + 1], al[mf], bh + 2);
                }
            }
        }
    };

    // ================= GEMM1 =================
    if (MODE != 0) {
        issueA(0, 0); issueB1(0, 0); CPCOMMIT();
#pragma unroll 1
        for (int c = 0; c < NC1; c++) {
            if (c + 1 < NC1) { issueA(c + 1, (c + 1) & 1); issueB1(c + 1, (c + 1) & 1); CPCOMMIT(); CPWAIT1(); }
            else CPWAIT0();
            __syncthreads();
            mma1(c & 1, 2);
            __syncthreads();
        }
    } else {
        {
            int row = row0 + cr;
            float v[8];
#pragma unroll
            for (int j = 0; j < 8; j++) {
                int k = cq * 8 + j;
                v[j] = (row < nrows && k < KIN) ? in0[(size_t)row * KIN + k] : 0.f;
            }
            uint4 hv, lv;
            hv.x = packh(v[0], v[1]); lv.x = packl(v[0], v[1], hv.x);
            hv.y = packh(v[2], v[3]); lv.y = packl(v[2], v[3], hv.y);
            hv.z = packh(v[4], v[5]); lv.z = packl(v[4], v[5], hv.z);
            hv.w = packh(v[6], v[7]); lv.w = packl(v[6], v[7], hv.w);
            *(uint4*)(dsm + cr * 80 + cq * 16) = hv;
            *(uint4*)(dsm + 10240 + cr * 80 + cq * 16) = lv;
            *(uint4*)(dsm + 69632 + cr * 80 + cq * 16) = *(const uint4*)(g_whi + w0eff + cr * 32 + cq * 8);
            *(uint4*)(dsm + 69632 + 10240 + cr * 80 + cq * 16) = *(const uint4*)(g_wlo + w0eff + cr * 32 + cq * 8);
        }
        __syncthreads();
        mma1(0, 1);
        __syncthreads();
    }

    // ================= MODE 4: store fp32 product, done =================
    if (MODE == 4) {
#pragma unroll
        for (int mf = 0; mf < 2; mf++)
#pragma unroll
            for (int nf = 0; nf < 4; nf++) {
                int r0 = mr + mf * 16 + g4, c0 = nc + nf * 8 + 2 * t4;
                int row1 = row0 + r0, row2 = row1 + 8;
                if (row1 < nrows)
                    *(float2*)(out4 + (size_t)row1 * 128 + c0) = make_float2(acc[mf][nf][0], acc[mf][nf][1]);
                if (row2 < nrows)
                    *(float2*)(out4 + (size_t)row2 * 128 + c0) = make_float2(acc[mf][nf][2], acc[mf][nf][3]);
            }
        return;
    }

    // prefetch first GEMM2 B chunk (overlaps epilogue 1)
    if (MODE != 3) { issueB2(0, 0); CPCOMMIT(); }

    // ================= epilogue 1: bias (+PS/PR for edges) + gelu =================
    if (MODE == 3) {
#pragma unroll
        for (int mf = 0; mf < 2; mf++)
#pragma unroll
            for (int nf = 0; nf < 4; nf++) {
                int r0 = mr + mf * 16 + g4, c0 = nc + nf * 8 + 2 * t4;
                sD[r0 * 132 + c0]           = gelu_f(acc[mf][nf][0] + sb0[c0]);
                sD[r0 * 132 + c0 + 1]       = gelu_f(acc[mf][nf][1] + sb0[c0 + 1]);
                sD[(r0 + 8) * 132 + c0]     = gelu_f(acc[mf][nf][2] + sb0[c0]);
                sD[(r0 + 8) * 132 + c0 + 1] = gelu_f(acc[mf][nf][3] + sb0[c0 + 1]);
            }
        __syncthreads();
        for (int i = tid; i < 128 * 3; i += NT) {
            int r = i / 3, cc = i - r * 3;
            int row = row0 + r;
            if (row < nrows) {
                float s = sb1[cc];
                const float* hr = sD + r * 132;
#pragma unroll 4
                for (int k = 0; k < 128; k++) s += hr[k] * __ldg(in0 + k * 3 + cc);
                outp[(size_t)row * 3 + cc] = s;
            }
        }
        return;
    }

    {
        uint32_t* A2hw = (uint32_t*)dsm;
        uint32_t* A2lw = (uint32_t*)(dsm + 34816);
#pragma unroll
        for (int mf = 0; mf < 2; mf++)
#pragma unroll
            for (int nf = 0; nf < 4; nf++) {
                int r0 = mr + mf * 16 + g4, c0 = nc + nf * 8 + 2 * t4;
                float a0 = acc[mf][nf][0] + sb0[c0];
                float a1 = acc[mf][nf][1] + sb0[c0 + 1];
                float a2 = acc[mf][nf][2] + sb0[c0];
                float a3 = acc[mf][nf][3] + sb0[c0 + 1];
                if (MODE == 1) {
                    float2 p0 = *(const float2*)(psp + (size_t)snd_sh[r0] * 128 + c0);
                    float2 q0 = *(const float2*)(prp + (size_t)rcv_sh[r0] * 128 + c0);
                    float2 p1 = *(const float2*)(psp + (size_t)snd_sh[r0 + 8] * 128 + c0);
                    float2 q1 = *(const float2*)(prp + (size_t)rcv_sh[r0 + 8] * 128 + c0);
                    a0 += p0.x + q0.x; a1 += p0.y + q0.y;
                    a2 += p1.x + q1.x; a3 += p1.y + q1.y;
                }
                float v0 = gelu_f(a0), v1 = gelu_f(a1), v2 = gelu_f(a2), v3 = gelu_f(a3);
                uint32_t h0 = packh(v0, v1), l0 = packl(v0, v1, h0);
                uint32_t h1 = packh(v2, v3), l1 = packl(v2, v3, h1);
                A2hw[r0 * 68 + (c0 >> 1)] = h0;       A2lw[r0 * 68 + (c0 >> 1)] = l0;
                A2hw[(r0 + 8) * 68 + (c0 >> 1)] = h1; A2lw[(r0 + 8) * 68 + (c0 >> 1)] = l1;
            }
    }
    __syncthreads();

    // ================= GEMM2: A2[128x128] @ W1 (B pipelined) =================
#pragma unroll
    for (int mf = 0; mf < 2; mf++)
#pragma unroll
        for (int nf = 0; nf < 4; nf++)
#pragma unroll
            for (int q = 0; q < 4; q++) acc[mf][nf][q] = 0.f;

#pragma unroll 1
    for (int c = 0; c < 4; c++) {
        if (c + 1 < 4) { issueB2(c + 1, (c + 1) & 1); CPCOMMIT(); CPWAIT1(); }
        else CPWAIT0();
        __syncthreads();
#pragma unroll
        for (int ks = 0; ks < 2; ks++) {
            uint32_t ah[2][4], al[2][4];
#pragma unroll
            for (int mf = 0; mf < 2; mf++) {
                uint32_t ra = uA + (uint32_t)(mr + mf * 16 + a_row) * 272u + (uint32_t)c * 64u + (uint32_t)ks * 32u + a_ko;
                ldm4(ah[mf], ra);
                ldm4(al[mf], ra + 34816);
            }
#pragma unroll
            for (int np = 0; np < 2; np++) {
                uint32_t bh[4], bl[4];
                uint32_t rb = uB + (uint32_t)((c & 1)) * 20480u + (uint32_t)(nc + np * 16 + b_row) * 80u + (uint32_t)ks * 32u + b_ko;
                ldm4(bh, rb);
                ldm4(bl, rb + 10240);
#pragma unroll
                for (int mf = 0; mf < 2; mf++) {
                    mmabf(acc[mf][np * 2],     ah[mf], bh);
                    mmabf(acc[mf][np * 2],     ah[mf], bl);
                    mmabf(acc[mf][np * 2],     al[mf], bh);
                    mmabf(acc[mf][np * 2 + 1], ah[mf], bh + 2);
                    mmabf(acc[mf][np * 2 + 1], ah[mf], bl + 2);
                    mmabf(acc[mf][np * 2 + 1], al[mf], bh + 2);
                }
            }
        }
        __syncthreads();
    }

    // ================= epilogue 2 =================
    if (MODE == 0) {
#pragma unroll
        for (int mf = 0; mf < 2; mf++)
#pragma unroll
            for (int nf = 0; nf < 4; nf++) {
                int r0 = mr + mf * 16 + g4, c0 = nc + nf * 8 + 2 * t4;
                int row1 = row0 + r0, row2 = row1 + 8;
                float v0 = acc[mf][nf][0] + sb1[c0], v1 = acc[mf][nf][1] + sb1[c0 + 1];
                float v2 = acc[mf][nf][2] + sb1[c0], v3 = acc[mf][nf][3] + sb1[c0 + 1];
                if (row1 < nrows) {
                    uint32_t h = packh(v0, v1);
                    *(uint32_t*)(outh + (size_t)row1 * 128 + c0) = h;
                    *(uint32_t*)(outl + (size_t)row1 * 128 + c0) = packl(v0, v1, h);
                }
                if (row2 < nrows) {
                    uint32_t h = packh(v2, v3);
                    *(uint32_t*)(outh + (size_t)row2 * 128 + c0) = h;
                    *(uint32_t*)(outl + (size_t)row2 * 128 + c0) = packl(v2, v3, h);
                }
            }
        return;
    }

#pragma unroll
    for (int mf = 0; mf < 2; mf++)
#pragma unroll
        for (int nf = 0; nf < 4; nf++) {
            int r0 = mr + mf * 16 + g4, c0 = nc + nf * 8 + 2 * t4;
            sD[r0 * 132 + c0]           = acc[mf][nf][0] + sb1[c0];
            sD[r0 * 132 + c0 + 1]       = acc[mf][nf][1] + sb1[c0 + 1];
            sD[(r0 + 8) * 132 + c0]     = acc[mf][nf][2] + sb1[c0];
            sD[(r0 + 8) * 132 + c0 + 1] = acc[mf][nf][3] + sb1[c0 + 1];
        }
    __syncthreads();

    if (MODE == 1) {
        for (int i = tid; i < 128 * 32; i += NT) {
            int r = i >> 5, q = i & 31;
            int row = row0 + r;
            if (row < nrows) {
                float4 v = *(float4*)(sD + r * 132 + q * 4);
                red4(rca + (size_t)rcv_sh[r] * 128 + q * 4, v);
            }
        }
    }
    if (write_ln) {
        float4 sc = *(const float4*)(lnsc + lane * 4);
        float4 bsv = *(const float4*)(lnbs + lane * 4);
        const __nv_bfloat16* skh = (MODE == 1) ? ehh : nhh;
        const __nv_bfloat16* skl = (MODE == 1) ? ehl : nhl;
        for (int r = warp; r < 128; r += 16) {
            int row = row0 + r;
            float4 x = *(float4*)(sD + r * 132 + lane * 4);
            if (row < nrows) {
                uint2 hh = *(const uint2*)(skh + (size_t)row * 128 + lane * 4);
                uint2 ll = *(const uint2*)(skl + (size_t)row * 128 + lane * 4);
                x.x += rec2(hh.x, ll.x, 0); x.y += rec2(hh.x, ll.x, 1);
                x.z += rec2(hh.y, ll.y, 0); x.w += rec2(hh.y, ll.y, 1);
            }
            float s = wred(x.x + x.y + x.z + x.w);
            float mean = s * (1.f / 128.f);
            float dx = x.x - mean, dy = x.y - mean, dz = x.z - mean, dw = x.w - mean;
            float vv = wred(dx * dx + dy * dy + dz * dz + dw * dw);
            float inv = rsqrtf(vv * (1.f / 128.f) + 1e-6f);
            if (row < nrows) {
                float o0 = dx * inv * sc.x + bsv.x, o1 = dy * inv * sc.y + bsv.y;
                float o2 = dz * inv * sc.z + bsv.z, o3 = dw * inv * sc.w + bsv.w;
                uint32_t p0 = packh(o0, o1), p1 = packh(o2, o3);
                *(uint2*)(outh + (size_t)row * 128 + lane * 4) = make_uint2(p0, p1);
                *(uint2*)(outl + (size_t)row * 128 + lane * 4) =
                    make_uint2(packl(o0, o1, p0), packl(o2, o3, p1));
            }
        }
    }
}

extern "C" void kernel_launch(void* const* d_in, const int* in_sizes, int n_in,
                              void* d_out, int out_size)
{
    const float* nodes  = (const float*)d_in[0];
    const float* edges  = (const float*)d_in[1];
    const float* glob   = (const float*)d_in[2];
    const int*   snd    = (const int*)d_in[3];
    const int*   rcv    = (const int*)d_in[4];
    const float* ne_W0  = (const float*)d_in[5];
    const float* ne_b0  = (const float*)d_in[6];
    const float* ne_W1  = (const float*)d_in[7];
    const float* ne_b1  = (const float*)d_in[8];
    const float* ee_W0  = (const float*)d_in[9];
    const float* ee_b0  = (const float*)d_in[10];
    const float* ee_W1  = (const float*)d_in[11];
    const float* ee_b1  = (const float*)d_in[12];
    const float* eu_W0  = (const float*)d_in[13];
    const float* eu_b0  = (const float*)d_in[14];
    const float* eu_W1  = (const float*)d_in[15];
    const float* eu_b1  = (const float*)d_in[16];
    const float* nu_W0  = (const float*)d_in[17];
    const float* nu_b0  = (const float*)d_in[18];
    const float* nu_W1  = (const float*)d_in[19];
    const float* nu_b1  = (const float*)d_in[20];
    const float* lnsc   = (const float*)d_in[21];
    const float* lnbs   = (const float*)d_in[22];
    const float* dec_W0 = (const float*)d_in[23];
    const float* dec_b0 = (const float*)d_in[24];
    const float* dec_W1 = (const float*)d_in[25];
    const float* dec_b1 = (const float*)d_in[26];
    float* out = (float*)d_out;

    const int N = in_sizes[0] / 7;
    const int E = in_sizes[1] / 3;

    __nv_bfloat16 *nhh, *nhl, *ehh, *ehl, *rch, *rcl;
    float *rc, *b0p, *ps, *pr;
    cudaGetSymbolAddress((void**)&nhh, g_nhh);
    cudaGetSymbolAddress((void**)&nhl, g_nhl);
    cudaGetSymbolAddress((void**)&ehh, g_ehh);
    cudaGetSymbolAddress((void**)&ehl, g_ehl);
    cudaGetSymbolAddress((void**)&rch, g_rch);
    cudaGetSymbolAddress((void**)&rcl, g_rcl);
    cudaGetSymbolAddress((void**)&rc,  g_rc);
    cudaGetSymbolAddress((void**)&b0p, g_b0p);
    cudaGetSymbolAddress((void**)&ps,  g_ps);
    cudaGetSymbolAddress((void**)&pr,  g_pr);

    const int O_NEW0 = 0, O_NEW1 = 4096, O_EEW0 = 20480, O_EEW1 = 24576;
    const int O_WE0 = 40960, O_WS0 = 57344, O_WR0 = 73728, O_EUW1_0 = 90112;
    const int O_WE1 = 106496, O_WS1 = 122880, O_WR1 = 139264, O_EUW1_1 = 155648;
    const int O_NUW0_0 = 172032, O_NUW1_0 = 204800, O_NUW0_1 = 221184, O_NUW1_1 = 253952;
    const int O_DEC0 = 270336;

    prep_all<<<dim3(128, 17), 256>>>(
        ne_W0, ne_W1, ee_W0, ee_W1, eu_W0, eu_W1, nu_W0, nu_W1, dec_W0);
    bprep<<<4, 128>>>(eu_W0, eu_b0, nu_W0, nu_b0, glob);

    cudaFuncSetAttribute(gk<0, 1, 7>,   cudaFuncAttributeMaxDynamicSharedMemorySize, SMEMSZ);
    cudaFuncSetAttribute(gk<0, 1, 3>,   cudaFuncAttributeMaxDynamicSharedMemorySize, SMEMSZ);
    cudaFuncSetAttribute(gk<1, 4, 386>, cudaFuncAttributeMaxDynamicSharedMemorySize, SMEMSZ);
    cudaFuncSetAttribute(gk<2, 8, 258>, cudaFuncAttributeMaxDynamicSharedMemorySize, SMEMSZ);
    cudaFuncSetAttribute(gk<3, 4, 128>, cudaFuncAttributeMaxDynamicSharedMemorySize, SMEMSZ);
    cudaFuncSetAttribute(gk<4, 4, 128>, cudaFuncAttributeMaxDynamicSharedMemorySize, SMEMSZ);

    const int nbN = (N + 127) / 128;
    const int nbE = (E + 127) / 128;

    // zero both rc buffers (single async memset, graph-capturable)
    cudaMemsetAsync(rc, 0, (size_t)2 * N * 128 * sizeof(float));

    gk<0, 1, 7><<<nbN, NT, SMEMSZ>>>(N, nodes, O_NEW0, O_NEW1, ne_b0, ne_b1, nullptr,
        nhh, nhl, nullptr, nullptr, nhh, nhl, nullptr, nullptr, nullptr, nullptr,
        nullptr, nullptr, nullptr, nullptr, nullptr, 0);
    gk<0, 1, 3><<<nbE, NT, SMEMSZ>>>(E, edges, O_EEW0, O_EEW1, ee_b0, ee_b1, nullptr,
        ehh, ehl, nullptr, nullptr, nhh, nhl, nullptr, nullptr, nullptr, nullptr,
        nullptr, nullptr, nullptr, nullptr, nullptr, 0);

    for (int s = 0; s < 2; s++) {
        float* rcs = rc + (size_t)s * N * 128;
        // fused PS/PR precompute: grid.y=0 -> W_s -> ps, grid.y=1 -> W_r -> pr
        gk<4, 4, 128><<<dim3(nbN, 2), NT, SMEMSZ>>>(N, nullptr,
            s ? O_WS1 : O_WS0, s ? O_WR1 : O_WR0, lnbs, lnbs, ps,
            nullptr, nullptr, nullptr, nullptr, nhh, nhl, nullptr, nullptr, nullptr, nullptr,
            nullptr, nullptr, pr, lnsc, lnbs, 0);
        gk<1, 4, 386><<<nbE, NT, SMEMSZ>>>(E, nullptr,
            s ? O_WE1 : O_WE0, s ? O_EUW1_1 : O_EUW1_0,
            b0p + s * 128, eu_b1 + s * 128, nullptr,
            ehh, ehl, snd, rcv, nhh, nhl, ehh, ehl, nullptr, nullptr,
            ps, pr, rcs, lnsc, lnbs, (s == 0) ? 1 : 0);
        rcsplit<<<(N * 64 + 255) / 256, 256>>>(rcs, rch, rcl, N * 64);
        gk<2, 8, 258><<<nbN, NT, SMEMSZ>>>(N, nullptr,
            s ? O_NUW0_1 : O_NUW0_0, s ? O_NUW1_1 : O_NUW1_0,
            b0p + (2 + s) * 128, nu_b1 + s * 128, nullptr,
            nhh, nhl, nullptr, nullptr, nhh, nhl, nullptr, nullptr, rch, rcl,
            nullptr, nullptr, nullptr, lnsc, lnbs, 1);
    }

    gk<3, 4, 128><<<nbN, NT, SMEMSZ>>>(N, dec_W1, O_DEC0, 0, dec_b0, dec_b1, out,
        nullptr, nullptr, nullptr, nullptr, nhh, nhl, nullptr, nullptr, nullptr, nullptr,
        nullptr, nullptr, nullptr, nullptr, nullptr, 0);
}

// round 17
// speedup vs baseline: 1.1287x; 1.0676x over previous
#include <cuda_runtime.h>
#include <cuda_bf16.h>
#include <stdint.h>

#define NT 512

// latent state stored pre-split as bf16 hi/lo
__device__ __nv_bfloat16 g_nhh[50000 * 128];
__device__ __nv_bfloat16 g_nhl[50000 * 128];
__device__ __nv_bfloat16 g_ehh[500000 * 128];
__device__ __nv_bfloat16 g_ehl[500000 * 128];
__device__ float g_rc[2 * 50000 * 128];
__device__ __nv_bfloat16 g_rch[50000 * 128];
__device__ __nv_bfloat16 g_rcl[50000 * 128];
__device__ float g_ps[50000 * 128];
__device__ float g_pr[50000 * 128];
__device__ float g_deg[50000];
__device__ __nv_bfloat16 g_whi[294912];
__device__ __nv_bfloat16 g_wlo[294912];
__device__ float g_b0p[4 * 128];

static __device__ __forceinline__ float gelu_f(float x) {
    float t = tanhf(0.7978845608028654f * (x + 0.044715f * x * x * x));
    return 0.5f * x * (1.0f + t);
}
static __device__ __forceinline__ float wred(float v) {
#pragma unroll
    for (int o = 16; o; o >>= 1) v += __shfl_xor_sync(0xffffffffu, v, o);
    return v;
}
static __device__ __forceinline__ uint32_t packh(float x, float y) {
    __nv_bfloat162 h; h.x = __float2bfloat16(x); h.y = __float2bfloat16(y);
    return *(uint32_t*)&h;
}
static __device__ __forceinline__ uint32_t packl(float x, float y, uint32_t hw) {
    __nv_bfloat162 hh = *(__nv_bfloat162*)&hw;
    __nv_bfloat162 l;
    l.x = __float2bfloat16(x - __bfloat162float(hh.x));
    l.y = __float2bfloat16(y - __bfloat162float(hh.y));
    return *(uint32_t*)&l;
}
static __device__ __forceinline__ void mmabf(float* d, const uint32_t* a, const uint32_t* b) {
    asm volatile(
        "mma.sync.aligned.m16n8k16.row.col.f32.bf16.bf16.f32 "
        "{%0,%1,%2,%3}, {%4,%5,%6,%7}, {%8,%9}, {%0,%1,%2,%3};"
        : "+f"(d[0]), "+f"(d[1]), "+f"(d[2]), "+f"(d[3])
        : "r"(a[0]), "r"(a[1]), "r"(a[2]), "r"(a[3]), "r"(b[0]), "r"(b[1]));
}
static __device__ __forceinline__ uint32_t s2u(const void* p) {
    return (uint32_t)__cvta_generic_to_shared(p);
}
static __device__ __forceinline__ void ldm4(uint32_t* r, uint32_t a) {
    asm volatile("ldmatrix.sync.aligned.m8n8.x4.shared.b16 {%0,%1,%2,%3}, [%4];"
        : "=r"(r[0]), "=r"(r[1]), "=r"(r[2]), "=r"(r[3]) : "r"(a));
}
static __device__ __forceinline__ void red4(float* dst, float4 v) {
    asm volatile("red.global.add.v4.f32 [%0], {%1,%2,%3,%4};"
        :: "l"(dst), "f"(v.x), "f"(v.y), "f"(v.z), "f"(v.w) : "memory");
}
static __device__ __forceinline__ float rec2(uint32_t h, uint32_t l, int hi) {
    __nv_bfloat162 hh = *(__nv_bfloat162*)&h;
    __nv_bfloat162 ll = *(__nv_bfloat162*)&l;
    return hi ? (__bfloat162float(hh.y) + __bfloat162float(ll.y))
              : (__bfloat162float(hh.x) + __bfloat162float(ll.x));
}
static __device__ __forceinline__ void cpa16(uint32_t d, const void* s, uint32_t sz) {
    asm volatile("cp.async.cg.shared.global [%0], [%1], 16, %2;"
        :: "r"(d), "l"(s), "r"(sz) : "memory");
}
#define CPCOMMIT() asm volatile("cp.async.commit_group;" ::: "memory")
#define CPWAIT1()  asm volatile("cp.async.wait_group 1;" ::: "memory")
#define CPWAIT0()  asm volatile("cp.async.wait_group 0;" ::: "memory")

// weight prep: 17 jobs — transpose W[K,128] -> [n][Kpad] bf16 hi/lo.
__global__ void prep_all(
    const float* q0, const float* q1, const float* q2, const float* q3,
    const float* q4, const float* q5, const float* q6, const float* q7,
    const float* q8)
{
    static const int SRC[17] = {0,1,2,3, 4,4,4,5, 4,4,4,5, 6,7,6,7, 8};
    static const int SOF[17] = {0,0,0,0, 0,16384,32768,0, 49408,65792,82176,16384, 0,0,33024,16384, 0};
    static const int KT[17]  = {7,128,3,128, 128,128,128,128, 128,128,128,128, 256,128,256,128, 128};
    static const int KPT[17] = {32,128,32,128, 128,128,128,128, 128,128,128,128, 256,128,256,128, 128};
    static const int OFT[17] = {0,4096,20480,24576, 40960,57344,73728,90112,
                                106496,122880,139264,155648, 172032,204800,221184,253952, 270336};
    const float* ws[9] = {q0,q1,q2,q3,q4,q5,q6,q7,q8};
    int j = blockIdx.y;
    int K = KT[j], Kpad = KPT[j], off = OFT[j];
    const float* W = ws[SRC[j]] + SOF[j];
    int idx = blockIdx.x * 256 + threadIdx.x;
    if (idx >= Kpad * 128) return;
    int k = idx >> 7, n = idx & 127;
    float x = (k < K) ? W[k * 128 + n] : 0.f;
    __nv_bfloat16 h = __float2bfloat16(x);
    __nv_bfloat16 l = __float2bfloat16(x - __bfloat162float(h));
    g_whi[off + n * Kpad + k] = h;
    g_wlo[off + n * Kpad + k] = l;
}

__global__ void bprep(const float* eu_W0, const float* eu_b0,
                      const float* nu_W0, const float* nu_b0, const float* glob) {
    int n = threadIdx.x;
    int l = blockIdx.x;
    float g0 = glob[0], g1 = glob[1];
    const float* W; const float* b; int K;
    if (l < 2) { W = eu_W0 + (size_t)l * 386 * 128; b = eu_b0 + l * 128; K = 386; }
    else       { W = nu_W0 + (size_t)(l - 2) * 258 * 128; b = nu_b0 + (l - 2) * 128; K = 258; }
    g_b0p[l * 128 + n] = b[n] + g0 * W[(size_t)(K - 2) * 128 + n] + g1 * W[(size_t)(K - 1) * 128 + n];
}

__global__ void degk(const int* __restrict__ rcv, float* __restrict__ deg, int E) {
    int i = blockIdx.x * 256 + threadIdx.x;
    if (i < E) atomicAdd(deg + rcv[i], 1.f);
}

__global__ void rcsplit(const float* rc, __nv_bfloat16* rh, __nv_bfloat16* rl, int n2) {
    int i = blockIdx.x * 256 + threadIdx.x;
    if (i < n2) {
        float2 v = ((const float2*)rc)[i];
        uint32_t h = packh(v.x, v.y), l = packl(v.x, v.y, h);
        ((uint32_t*)rh)[i] = h;
        ((uint32_t*)rl)[i] = l;
    }
}

// smem (bytes, base dsm):
//   A bufs:  2 x 20480 at 0      (per buf: hi +0, lo +10240; row stride 80)
//   B bufs:  2 x 20480 at 69632
//   A2:      hi 0..34816, lo 34816..69632 (row stride 272)
//   sD:      float[128][132] at 0
#define SMEMSZ 110592

// MODE 0: embed  1: edge step  2: node step  3: decode (in0 = dec_W1)
// MODE 4: N-row GEMM (ps/pr via grid.y, or S@W1+deg*b1 with split store)
// MODE 5: edge step LAST (GEMM1+gelu, atomically sum H; no GEMM2/LN)
template <int MODE, int NC1, int KIN>
__global__ void __launch_bounds__(NT, 2) gk(
    int nrows, const float* __restrict__ in0, int w0off, int w1off,
    const float* __restrict__ b0, const float* __restrict__ b1,
    float* __restrict__ outp,
    __nv_bfloat16* __restrict__ outh, __nv_bfloat16* __restrict__ outl,
    const int* __restrict__ snd, const int* __restrict__ rcv,
    const __nv_bfloat16* __restrict__ nhh, const __nv_bfloat16* __restrict__ nhl,
    const __nv_bfloat16* __restrict__ ehh, const __nv_bfloat16* __restrict__ ehl,
    const __nv_bfloat16* __restrict__ rch, const __nv_bfloat16* __restrict__ rcl,
    const float* __restrict__ psp, const float* __restrict__ prp,
    float* __restrict__ rca,
    const float* __restrict__ lnsc, const float* __restrict__ lnbs, int write_ln,
    const float* __restrict__ degp)
{
    extern __shared__ char dsm[];
    float* sD = (float*)dsm;
    __shared__ int snd_sh[128], rcv_sh[128];
    __shared__ float sb0[128], sb1[128];

    const int tid = threadIdx.x, lane = tid & 31, warp = tid >> 5;
    const int row0 = blockIdx.x * 128;
    const int mr = (warp & 3) * 32, nc = (warp >> 2) * 32;
    const int g4 = lane >> 2, t4 = lane & 3;

    // MODE 4: blockIdx.y selects (w0off -> outp) vs (w1off -> rca-as-output)
    const int w0eff = (MODE == 4 && blockIdx.y) ? w1off : w0off;
    float* out4 = (MODE == 4 && blockIdx.y) ? rca : outp;

    const uint32_t uA = s2u(dsm);
    const uint32_t uB = uA + 69632;

    if (tid < 128) {
        sb0[tid] = b0[tid];
        if (MODE == 1 || MODE == 5) snd_sh[tid] = (row0 + tid < nrows) ? snd[row0 + tid] : 0;
    } else if (tid < 256) {
        int j = tid - 128;
        if (MODE == 3) { if (j < 3) sb1[j] = b1[j]; }
        else sb1[j] = b1[j];
        if (MODE == 1 || MODE == 5) rcv_sh[j] = (row0 + j < nrows) ? rcv[row0 + j] : 0;
    }
    __syncthreads();

    const uint32_t a_row = (uint32_t)(lane & 15);
    const uint32_t a_ko  = (uint32_t)(lane >> 4) * 16u;
    const uint32_t b_row = (uint32_t)((lane & 7) + ((lane >> 4) << 3));
    const uint32_t b_ko  = (uint32_t)((lane >> 3) & 1) * 16u;

    const int cr = tid >> 2, cq = tid & 3;

    auto issueA = [&](int c, int bb) {
        int row = row0 + cr;
        int ko = cq * 8;
        const __nv_bfloat16 *ph, *pl;
        if (MODE == 1 || MODE == 5) {
            size_t o = (size_t)row * 128 + c * 32 + ko; ph = ehh + o; pl = ehl + o;
        } else if (MODE == 2) {
            if (c < 4) { size_t o = (size_t)row * 128 + c * 32 + ko; ph = nhh + o; pl = nhl + o; }
            else       { size_t o = (size_t)row * 128 + (c - 4) * 32 + ko; ph = rch + o; pl = rcl + o; }
        } else {
            size_t o = (size_t)row * 128 + c * 32 + ko; ph = nhh + o; pl = nhl + o;
        }
        uint32_t sz = (row < nrows) ? 16u : 0u;
        uint32_t d = uA + bb * 20480 + cr * 80 + cq * 16;
        cpa16(d, ph, sz);
        cpa16(d + 10240, pl, sz);
    };
    auto issueB1 = [&](int c, int bb) {
        size_t o = (size_t)w0eff + (size_t)cr * (NC1 * 32) + c * 32 + cq * 8;
        uint32_t d = uB + bb * 20480 + cr * 80 + cq * 16;
        cpa16(d, g_whi + o, 16);
        cpa16(d + 10240, g_wlo + o, 16);
    };
    auto issueB2 = [&](int c, int bb) {
        size_t o = (size_t)w1off + (size_t)cr * 128 + c * 32 + cq * 8;
        uint32_t d = uB + bb * 20480 + cr * 80 + cq * 16;
        cpa16(d, g_whi + o, 16);
        cpa16(d + 10240, g_wlo + o, 16);
    };

    float acc[2][4][4];
#pragma unroll
    for (int mf = 0; mf < 2; mf++)
#pragma unroll
        for (int nf = 0; nf < 4; nf++)
#pragma unroll
            for (int q = 0; q < 4; q++) acc[mf][nf][q] = 0.f;

    auto mma1 = [&](int bb, int nks) {
#pragma unroll
        for (int ks = 0; ks < 2; ks++) {
            if (ks >= nks) break;
            uint32_t ah[2][4], al[2][4];
#pragma unroll
            for (int mf = 0; mf < 2; mf++) {
                uint32_t ra = uA + bb * 20480 + (uint32_t)(mr + mf * 16 + a_row) * 80u + (uint32_t)ks * 32u + a_ko;
                ldm4(ah[mf], ra);
                ldm4(al[mf], ra + 10240);
            }
#pragma unroll
            for (int np = 0; np < 2; np++) {
                uint32_t bh[4], bl[4];
                uint32_t rb = uB + bb * 20480 + (uint32_t)(nc + np * 16 + b_row) * 80u + (uint32_t)ks * 32u + b_ko;
                ldm4(bh, rb);
                ldm4(bl, rb + 10240);
#pragma unroll
                for (int mf = 0; mf < 2; mf++) {
                    mmabf(acc[mf][np * 2],     ah[mf], bh);
                    mmabf(acc[mf][np * 2],     ah[mf], bl);
                    mmabf(acc[mf][np * 2],     al[mf], bh);
                    mmabf(acc[mf][np * 2 + 1], ah[mf], bh + 2);
                    mmabf(acc[mf][np * 2 + 1], ah[mf], bl + 2);
                    mmabf(acc[mf][np * 2 + 1], al[mf], bh + 2);
                }
            }
        }
    };

    // ================= GEMM1 =================
    if (MODE != 0) {
        issueA(0, 0); issueB1(0, 0); CPCOMMIT();
#pragma unroll 1
        for (int c = 0; c < NC1; c++) {
            if (c + 1 < NC1) { issueA(c + 1, (c + 1) & 1); issueB1(c + 1, (c + 1) & 1); CPCOMMIT(); CPWAIT1(); }
            else CPWAIT0();
            __syncthreads();
            mma1(c & 1, 2);
            __syncthreads();
        }
    } else {
        {
            int row = row0 + cr;
            float v[8];
#pragma unroll
            for (int j = 0; j < 8; j++) {
                int k = cq * 8 + j;
                v[j] = (row < nrows && k < KIN) ? in0[(size_t)row * KIN + k] : 0.f;
            }
            uint4 hv, lv;
            hv.x = packh(v[0], v[1]); lv.x = packl(v[0], v[1], hv.x);
            hv.y = packh(v[2], v[3]); lv.y = packl(v[2], v[3], hv.y);
            hv.z = packh(v[4], v[5]); lv.z = packl(v[4], v[5], hv.z);
            hv.w = packh(v[6], v[7]); lv.w = packl(v[6], v[7], hv.w);
            *(uint4*)(dsm + cr * 80 + cq * 16) = hv;
            *(uint4*)(dsm + 10240 + cr * 80 + cq * 16) = lv;
            *(uint4*)(dsm + 69632 + cr * 80 + cq * 16) = *(const uint4*)(g_whi + w0eff + cr * 32 + cq * 8);
            *(uint4*)(dsm + 69632 + 10240 + cr * 80 + cq * 16) = *(const uint4*)(g_wlo + w0eff + cr * 32 + cq * 8);
        }
        __syncthreads();
        mma1(0, 1);
        __syncthreads();
    }

    // ================= MODE 4: store product (fp32 or split bf16), done =================
    if (MODE == 4) {
#pragma unroll
        for (int mf = 0; mf < 2; mf++)
#pragma unroll
            for (int nf = 0; nf < 4; nf++) {
                int r0 = mr + mf * 16 + g4, c0 = nc + nf * 8 + 2 * t4;
                int row1 = row0 + r0, row2 = row1 + 8;
                float v0 = acc[mf][nf][0], v1 = acc[mf][nf][1];
                float v2 = acc[mf][nf][2], v3 = acc[mf][nf][3];
                if (degp) {
                    float d1 = (row1 < nrows) ? degp[row1] : 0.f;
                    float d2 = (row2 < nrows) ? degp[row2] : 0.f;
                    v0 += d1 * sb1[c0]; v1 += d1 * sb1[c0 + 1];
                    v2 += d2 * sb1[c0]; v3 += d2 * sb1[c0 + 1];
                }
                if (outh) {
                    if (row1 < nrows) {
                        uint32_t h = packh(v0, v1);
                        *(uint32_t*)(outh + (size_t)row1 * 128 + c0) = h;
                        *(uint32_t*)(outl + (size_t)row1 * 128 + c0) = packl(v0, v1, h);
                    }
                    if (row2 < nrows) {
                        uint32_t h = packh(v2, v3);
                        *(uint32_t*)(outh + (size_t)row2 * 128 + c0) = h;
                        *(uint32_t*)(outl + (size_t)row2 * 128 + c0) = packl(v2, v3, h);
                    }
                } else {
                    if (row1 < nrows)
                        *(float2*)(out4 + (size_t)row1 * 128 + c0) = make_float2(v0, v1);
                    if (row2 < nrows)
                        *(float2*)(out4 + (size_t)row2 * 128 + c0) = make_float2(v2, v3);
                }
            }
        return;
    }

    // ================= MODE 5: gelu + PS/PR, atomically sum H, done =================
    if (MODE == 5) {
#pragma unroll
        for (int mf = 0; mf < 2; mf++)
#pragma unroll
            for (int nf = 0; nf < 4; nf++) {
                int r0 = mr + mf * 16 + g4, c0 = nc + nf * 8 + 2 * t4;
                float a0 = acc[mf][nf][0] + sb0[c0];
                float a1 = acc[mf][nf][1] + sb0[c0 + 1];
                float a2 = acc[mf][nf][2] + sb0[c0];
                float a3 = acc[mf][nf][3] + sb0[c0 + 1];
                float2 p0 = *(const float2*)(psp + (size_t)snd_sh[r0] * 128 + c0);
                float2 q0 = *(const float2*)(prp + (size_t)rcv_sh[r0] * 128 + c0);
                float2 p1 = *(const float2*)(psp + (size_t)snd_sh[r0 + 8] * 128 + c0);
                float2 q1 = *(const float2*)(prp + (size_t)rcv_sh[r0 + 8] * 128 + c0);
                a0 += p0.x + q0.x; a1 += p0.y + q0.y;
                a2 += p1.x + q1.x; a3 += p1.y + q1.y;
                sD[r0 * 132 + c0]           = gelu_f(a0);
                sD[r0 * 132 + c0 + 1]       = gelu_f(a1);
                sD[(r0 + 8) * 132 + c0]     = gelu_f(a2);
                sD[(r0 + 8) * 132 + c0 + 1] = gelu_f(a3);
            }
        __syncthreads();
        for (int i = tid; i < 128 * 32; i += NT) {
            int r = i >> 5, q = i & 31;
            int row = row0 + r;
            if (row < nrows) {
                float4 v = *(float4*)(sD + r * 132 + q * 4);
                red4(rca + (size_t)rcv_sh[r] * 128 + q * 4, v);
            }
        }
        return;
    }

    // prefetch first GEMM2 B chunk (overlaps epilogue 1)
    if (MODE != 3) { issueB2(0, 0); CPCOMMIT(); }

    // ================= epilogue 1: bias (+PS/PR for edges) + gelu =================
    if (MODE == 3) {
#pragma unroll
        for (int mf = 0; mf < 2; mf++)
#pragma unroll
            for (int nf = 0; nf < 4; nf++) {
                int r0 = mr + mf * 16 + g4, c0 = nc + nf * 8 + 2 * t4;
                sD[r0 * 132 + c0]           = gelu_f(acc[mf][nf][0] + sb0[c0]);
                sD[r0 * 132 + c0 + 1]       = gelu_f(acc[mf][nf][1] + sb0[c0 + 1]);
                sD[(r0 + 8) * 132 + c0]     = gelu_f(acc[mf][nf][2] + sb0[c0]);
                sD[(r0 + 8) * 132 + c0 + 1] = gelu_f(acc[mf][nf][3] + sb0[c0 + 1]);
            }
        __syncthreads();
        for (int i = tid; i < 128 * 3; i += NT) {
            int r = i / 3, cc = i - r * 3;
            int row = row0 + r;
            if (row < nrows) {
                float s = sb1[cc];
                const float* hr = sD + r * 132;
#pragma unroll 4
                for (int k = 0; k < 128; k++) s += hr[k] * __ldg(in0 + k * 3 + cc);
                outp[(size_t)row * 3 + cc] = s;
            }
        }
        return;
    }

    {
        uint32_t* A2hw = (uint32_t*)dsm;
        uint32_t* A2lw = (uint32_t*)(dsm + 34816);
#pragma unroll
        for (int mf = 0; mf < 2; mf++)
#pragma unroll
            for (int nf = 0; nf < 4; nf++) {
                int r0 = mr + mf * 16 + g4, c0 = nc + nf * 8 + 2 * t4;
                float a0 = acc[mf][nf][0] + sb0[c0];
                float a1 = acc[mf][nf][1] + sb0[c0 + 1];
                float a2 = acc[mf][nf][2] + sb0[c0];
                float a3 = acc[mf][nf][3] + sb0[c0 + 1];
                if (MODE == 1) {
                    float2 p0 = *(const float2*)(psp + (size_t)snd_sh[r0] * 128 + c0);
                    float2 q0 = *(const float2*)(prp + (size_t)rcv_sh[r0] * 128 + c0);
                    float2 p1 = *(const float2*)(psp + (size_t)snd_sh[r0 + 8] * 128 + c0);
                    float2 q1 = *(const float2*)(prp + (size_t)rcv_sh[r0 + 8] * 128 + c0);
                    a0 += p0.x + q0.x; a1 += p0.y + q0.y;
                    a2 += p1.x + q1.x; a3 += p1.y + q1.y;
                }
                float v0 = gelu_f(a0), v1 = gelu_f(a1), v2 = gelu_f(a2), v3 = gelu_f(a3);
                uint32_t h0 = packh(v0, v1), l0 = packl(v0, v1, h0);
                uint32_t h1 = packh(v2, v3), l1 = packl(v2, v3, h1);
                A2hw[r0 * 68 + (c0 >> 1)] = h0;       A2lw[r0 * 68 + (c0 >> 1)] = l0;
                A2hw[(r0 + 8) * 68 + (c0 >> 1)] = h1; A2lw[(r0 + 8) * 68 + (c0 >> 1)] = l1;
            }
    }
    __syncthreads();

    // ================= GEMM2: A2[128x128] @ W1 (B pipelined) =================
#pragma unroll
    for (int mf = 0; mf < 2; mf++)
#pragma unroll
        for (int nf = 0; nf < 4; nf++)
#pragma unroll
            for (int q = 0; q < 4; q++) acc[mf][nf][q] = 0.f;

#pragma unroll 1
    for (int c = 0; c < 4; c++) {
        if (c + 1 < 4) { issueB2(c + 1, (c + 1) & 1); CPCOMMIT(); CPWAIT1(); }
        else CPWAIT0();
        __syncthreads();
#pragma unroll
        for (int ks = 0; ks < 2; ks++) {
            uint32_t ah[2][4], al[2][4];
#pragma unroll
            for (int mf = 0; mf < 2; mf++) {
                uint32_t ra = uA + (uint32_t)(mr + mf * 16 + a_row) * 272u + (uint32_t)c * 64u + (uint32_t)ks * 32u + a_ko;
                ldm4(ah[mf], ra);
                ldm4(al[mf], ra + 34816);
            }
#pragma unroll
            for (int np = 0; np < 2; np++) {
                uint32_t bh[4], bl[4];
                uint32_t rb = uB + (uint32_t)((c & 1)) * 20480u + (uint32_t)(nc + np * 16 + b_row) * 80u + (uint32_t)ks * 32u + b_ko;
                ldm4(bh, rb);
                ldm4(bl, rb + 10240);
#pragma unroll
                for (int mf = 0; mf < 2; mf++) {
                    mmabf(acc[mf][np * 2],     ah[mf], bh);
                    mmabf(acc[mf][np * 2],     ah[mf], bl);
                    mmabf(acc[mf][np * 2],     al[mf], bh);
                    mmabf(acc[mf][np * 2 + 1], ah[mf], bh + 2);
                    mmabf(acc[mf][np * 2 + 1], ah[mf], bl + 2);
                    mmabf(acc[mf][np * 2 + 1], al[mf], bh + 2);
                }
            }
        }
        __syncthreads();
    }

    // ================= epilogue 2 =================
    if (MODE == 0) {
#pragma unroll
        for (int mf = 0; mf < 2; mf++)
#pragma unroll
            for (int nf = 0; nf < 4; nf++) {
                int r0 = mr + mf * 16 + g4, c0 = nc + nf * 8 + 2 * t4;
                int row1 = row0 + r0, row2 = row1 + 8;
                float v0 = acc[mf][nf][0] + sb1[c0], v1 = acc[mf][nf][1] + sb1[c0 + 1];
                float v2 = acc[mf][nf][2] + sb1[c0], v3 = acc[mf][nf][3] + sb1[c0 + 1];
                if (row1 < nrows) {
                    uint32_t h = packh(v0, v1);
                    *(uint32_t*)(outh + (size_t)row1 * 128 + c0) = h;
                    *(uint32_t*)(outl + (size_t)row1 * 128 + c0) = packl(v0, v1, h);
                }
                if (row2 < nrows) {
                    uint32_t h = packh(v2, v3);
                    *(uint32_t*)(outh + (size_t)row2 * 128 + c0) = h;
                    *(uint32_t*)(outl + (size_t)row2 * 128 + c0) = packl(v2, v3, h);
                }
            }
        return;
    }

#pragma unroll
    for (int mf = 0; mf < 2; mf++)
#pragma unroll
        for (int nf = 0; nf < 4; nf++) {
            int r0 = mr + mf * 16 + g4, c0 = nc + nf * 8 + 2 * t4;
            sD[r0 * 132 + c0]           = acc[mf][nf][0] + sb1[c0];
            sD[r0 * 132 + c0 + 1]       = acc[mf][nf][1] + sb1[c0 + 1];
            sD[(r0 + 8) * 132 + c0]     = acc[mf][nf][2] + sb1[c0];
            sD[(r0 + 8) * 132 + c0 + 1] = acc[mf][nf][3] + sb1[c0 + 1];
        }
    __syncthreads();

    if (MODE == 1) {
        for (int i = tid; i < 128 * 32; i += NT) {
            int r = i >> 5, q = i & 31;
            int row = row0 + r;
            if (row < nrows) {
                float4 v = *(float4*)(sD + r * 132 + q * 4);
                red4(rca + (size_t)rcv_sh[r] * 128 + q * 4, v);
            }
        }
    }
    if (write_ln) {
        float4 sc = *(const float4*)(lnsc + lane * 4);
        float4 bsv = *(const float4*)(lnbs + lane * 4);
        const __nv_bfloat16* skh = (MODE == 1) ? ehh : nhh;
        const __nv_bfloat16* skl = (MODE == 1) ? ehl : nhl;
        for (int r = warp; r < 128; r += 16) {
            int row = row0 + r;
            float4 x = *(float4*)(sD + r * 132 + lane * 4);
            if (row < nrows) {
                uint2 hh = *(const uint2*)(skh + (size_t)row * 128 + lane * 4);
                uint2 ll = *(const uint2*)(skl + (size_t)row * 128 + lane * 4);
                x.x += rec2(hh.x, ll.x, 0); x.y += rec2(hh.x, ll.x, 1);
                x.z += rec2(hh.y, ll.y, 0); x.w += rec2(hh.y, ll.y, 1);
            }
            float s = wred(x.x + x.y + x.z + x.w);
            float mean = s * (1.f / 128.f);
            float dx = x.x - mean, dy = x.y - mean, dz = x.z - mean, dw = x.w - mean;
            float vv = wred(dx * dx + dy * dy + dz * dz + dw * dw);
            float inv = rsqrtf(vv * (1.f / 128.f) + 1e-6f);
            if (row < nrows) {
                float o0 = dx * inv * sc.x + bsv.x, o1 = dy * inv * sc.y + bsv.y;
                float o2 = dz * inv * sc.z + bsv.z, o3 = dw * inv * sc.w + bsv.w;
                uint32_t p0 = packh(o0, o1), p1 = packh(o2, o3);
                *(uint2*)(outh + (size_t)row * 128 + lane * 4) = make_uint2(p0, p1);
                *(uint2*)(outl + (size_t)row * 128 + lane * 4) =
                    make_uint2(packl(o0, o1, p0), packl(o2, o3, p1));
            }
        }
    }
}

extern "C" void kernel_launch(void* const* d_in, const int* in_sizes, int n_in,
                              void* d_out, int out_size)
{
    const float* nodes  = (const float*)d_in[0];
    const float* edges  = (const float*)d_in[1];
    const float* glob   = (const float*)d_in[2];
    const int*   snd    = (const int*)d_in[3];
    const int*   rcv    = (const int*)d_in[4];
    const float* ne_W0  = (const float*)d_in[5];
    const float* ne_b0  = (const float*)d_in[6];
    const float* ne_W1  = (const float*)d_in[7];
    const float* ne_b1  = (const float*)d_in[8];
    const float* ee_W0  = (const float*)d_in[9];
    const float* ee_b0  = (const float*)d_in[10];
    const float* ee_W1  = (const float*)d_in[11];
    const float* ee_b1  = (const float*)d_in[12];
    const float* eu_W0  = (const float*)d_in[13];
    const float* eu_b0  = (const float*)d_in[14];
    const float* eu_W1  = (const float*)d_in[15];
    const float* eu_b1  = (const float*)d_in[16];
    const float* nu_W0  = (const float*)d_in[17];
    const float* nu_b0  = (const float*)d_in[18];
    const float* nu_W1  = (const float*)d_in[19];
    const float* nu_b1  = (const float*)d_in[20];
    const float* lnsc   = (const float*)d_in[21];
    const float* lnbs   = (const float*)d_in[22];
    const float* dec_W0 = (const float*)d_in[23];
    const float* dec_b0 = (const float*)d_in[24];
    const float* dec_W1 = (const float*)d_in[25];
    const float* dec_b1 = (const float*)d_in[26];
    float* out = (float*)d_out;

    const int N = in_sizes[0] / 7;
    const int E = in_sizes[1] / 3;

    __nv_bfloat16 *nhh, *nhl, *ehh, *ehl, *rch, *rcl;
    float *rc, *b0p, *ps, *pr, *deg;
    cudaGetSymbolAddress((void**)&nhh, g_nhh);
    cudaGetSymbolAddress((void**)&nhl, g_nhl);
    cudaGetSymbolAddress((void**)&ehh, g_ehh);
    cudaGetSymbolAddress((void**)&ehl, g_ehl);
    cudaGetSymbolAddress((void**)&rch, g_rch);
    cudaGetSymbolAddress((void**)&rcl, g_rcl);
    cudaGetSymbolAddress((void**)&rc,  g_rc);
    cudaGetSymbolAddress((void**)&b0p, g_b0p);
    cudaGetSymbolAddress((void**)&ps,  g_ps);
    cudaGetSymbolAddress((void**)&pr,  g_pr);
    cudaGetSymbolAddress((void**)&deg, g_deg);

    const int O_NEW0 = 0, O_NEW1 = 4096, O_EEW0 = 20480, O_EEW1 = 24576;
    const int O_WE0 = 40960, O_WS0 = 57344, O_WR0 = 73728, O_EUW1_0 = 90112;
    const int O_WE1 = 106496, O_WS1 = 122880, O_WR1 = 139264, O_EUW1_1 = 155648;
    const int O_NUW0_0 = 172032, O_NUW1_0 = 204800, O_NUW0_1 = 221184, O_NUW1_1 = 253952;
    const int O_DEC0 = 270336;

    prep_all<<<dim3(128, 17), 256>>>(
        ne_W0, ne_W1, ee_W0, ee_W1, eu_W0, eu_W1, nu_W0, nu_W1, dec_W0);
    bprep<<<4, 128>>>(eu_W0, eu_b0, nu_W0, nu_b0, glob);

    cudaFuncSetAttribute(gk<0, 1, 7>,   cudaFuncAttributeMaxDynamicSharedMemorySize, SMEMSZ);
    cudaFuncSetAttribute(gk<0, 1, 3>,   cudaFuncAttributeMaxDynamicSharedMemorySize, SMEMSZ);
    cudaFuncSetAttribute(gk<1, 4, 386>, cudaFuncAttributeMaxDynamicSharedMemorySize, SMEMSZ);
    cudaFuncSetAttribute(gk<5, 4, 386>, cudaFuncAttributeMaxDynamicSharedMemorySize, SMEMSZ);
    cudaFuncSetAttribute(gk<2, 8, 258>, cudaFuncAttributeMaxDynamicSharedMemorySize, SMEMSZ);
    cudaFuncSetAttribute(gk<3, 4, 128>, cudaFuncAttributeMaxDynamicSharedMemorySize, SMEMSZ);
    cudaFuncSetAttribute(gk<4, 4, 128>, cudaFuncAttributeMaxDynamicSharedMemorySize, SMEMSZ);

    const int nbN = (N + 127) / 128;
    const int nbE = (E + 127) / 128;

    cudaMemsetAsync(rc, 0, (size_t)2 * N * 128 * sizeof(float));
    cudaMemsetAsync(deg, 0, (size_t)N * sizeof(float));
    degk<<<(E + 255) / 256, 256>>>(rcv, deg, E);

    gk<0, 1, 7><<<nbN, NT, SMEMSZ>>>(N, nodes, O_NEW0, O_NEW1, ne_b0, ne_b1, nullptr,
        nhh, nhl, nullptr, nullptr, nhh, nhl, nullptr, nullptr, nullptr, nullptr,
        nullptr, nullptr, nullptr, nullptr, nullptr, 0, nullptr);
    gk<0, 1, 3><<<nbE, NT, SMEMSZ>>>(E, edges, O_EEW0, O_EEW1, ee_b0, ee_b1, nullptr,
        ehh, ehl, nullptr, nullptr, nhh, nhl, nullptr, nullptr, nullptr, nullptr,
        nullptr, nullptr, nullptr, nullptr, nullptr, 0, nullptr);

    for (int s = 0; s < 2; s++) {
        float* rcs = rc + (size_t)s * N * 128;
        // fused PS/PR precompute: grid.y=0 -> W_s -> ps, grid.y=1 -> W_r -> pr
        gk<4, 4, 128><<<dim3(nbN, 2), NT, SMEMSZ>>>(N, nullptr,
            s ? O_WS1 : O_WS0, s ? O_WR1 : O_WR0, lnbs, lnbs, ps,
            nullptr, nullptr, nullptr, nullptr, nhh, nhl, nullptr, nullptr, nullptr, nullptr,
            nullptr, nullptr, pr, lnsc, lnbs, 0, nullptr);
        if (s == 0) {
            gk<1, 4, 386><<<nbE, NT, SMEMSZ>>>(E, nullptr,
                O_WE0, O_EUW1_0, b0p, eu_b1, nullptr,
                ehh, ehl, snd, rcv, nhh, nhl, ehh, ehl, nullptr, nullptr,
                ps, pr, rcs, lnsc, lnbs, 1, nullptr);
            rcsplit<<<(N * 64 + 255) / 256, 256>>>(rcs, rch, rcl, N * 64);
        } else {
            // last step: sum H (gelu output) per receiver, then received = S@W1 + deg*b1
            gk<5, 4, 386><<<nbE, NT, SMEMSZ>>>(E, nullptr,
                O_WE1, 0, b0p + 128, eu_b1 + 128, nullptr,
                nullptr, nullptr, snd, rcv, nhh, nhl, ehh, ehl, nullptr, nullptr,
                ps, pr, rcs, lnsc, lnbs, 0, nullptr);
            rcsplit<<<(N * 64 + 255) / 256, 256>>>(rcs, rch, rcl, N * 64);
            // S@W1 + deg*b1, split-store in place into rch/rcl
            gk<4, 4, 128><<<nbN, NT, SMEMSZ>>>(N, nullptr,
                O_EUW1_1, 0, lnbs, eu_b1 + 128, nullptr,
                rch, rcl, nullptr, nullptr, rch, rcl, nullptr, nullptr, nullptr, nullptr,
                nullptr, nullptr, nullptr, lnsc, lnbs, 0, deg);
        }
        gk<2, 8, 258><<<nbN, NT, SMEMSZ>>>(N, nullptr,
            s ? O_NUW0_1 : O_NUW0_0, s ? O_NUW1_1 : O_NUW1_0,
            b0p + (2 + s) * 128, nu_b1 + s * 128, nullptr,
            nhh, nhl, nullptr, nullptr, nhh, nhl, nullptr, nullptr, rch, rcl,
            nullptr, nullptr, nullptr, lnsc, lnbs, 1, nullptr);
    }

    gk<3, 4, 128><<<nbN, NT, SMEMSZ>>>(N, dec_W1, O_DEC0, 0, dec_b0, dec_b1, out,
        nullptr, nullptr, nullptr, nullptr, nhh, nhl, nullptr, nullptr, nullptr, nullptr,
        nullptr, nullptr, nullptr, nullptr, nullptr, 0, nullptr);
}